// round 9
// baseline (speedup 1.0000x reference)
#include <cuda_runtime.h>
#include <cuda_bf16.h>
#include <mma.h>
#include <cstdint>

using namespace nvcuda;

#define Lc   8
#define Hc   4
#define Qc   64
#define Dc   512
#define Nc   2048
#define DFFc 2048

// ---------------- device scratch (no allocations allowed) ----------------
__device__ float g_X[Dc * Nc];
__device__ float g_attn[Dc * Nc];
__device__ float g_Y[Hc * Dc * Nc];
__device__ __nv_bfloat16 g_Kh[Lc * Hc * Qc * Dc],  g_Kl[Lc * Hc * Qc * Dc];
__device__ __nv_bfloat16 g_Vh[Lc * Hc * Dc * Dc],  g_Vl[Lc * Hc * Dc * Dc];
__device__ __nv_bfloat16 g_W1h[Lc * DFFc * Dc],    g_W1l[Lc * DFFc * Dc];
__device__ __nv_bfloat16 g_W2h[Lc * Dc * DFFc],    g_W2l[Lc * Dc * DFFc];
__device__ __nv_bfloat16 g_Xh[Dc * Nc],            g_Xl[Dc * Nc];
__device__ __nv_bfloat16 g_Ath[Dc * Nc],           g_Atl[Dc * Nc];
__device__ __nv_bfloat16 g_F1h[DFFc * Nc],         g_F1l[DFFc * Nc];
__device__ __nv_bfloat16 g_KXh[Hc * Qc * Nc],      g_KXl[Hc * Qc * Nc];

// ---------------- helpers --------------------------------------------------
__device__ __forceinline__ uint32_t smem_u32(const void* p) {
    uint32_t a;
    asm("{ .reg .u64 t; cvta.to.shared.u64 t, %1; cvt.u32.u64 %0, t; }"
        : "=r"(a) : "l"(p));
    return a;
}
__device__ __forceinline__ void cp16(void* s, const void* g) {
    asm volatile("cp.async.cg.shared.global [%0], [%1], 16;"
                 :: "r"(smem_u32(s)), "l"(g) : "memory");
}
__device__ __forceinline__ void cp_commit() {
    asm volatile("cp.async.commit_group;" ::: "memory");
}
template<int N> __device__ __forceinline__ void cp_wait() {
    asm volatile("cp.async.wait_group %0;" :: "n"(N) : "memory");
}

__device__ __forceinline__ void split_store4(__nv_bfloat16* __restrict__ Hd,
                                             __nv_bfloat16* __restrict__ Ld,
                                             float4 v)
{
    __nv_bfloat162 h0 = __floats2bfloat162_rn(v.x, v.y);
    __nv_bfloat162 h1 = __floats2bfloat162_rn(v.z, v.w);
    float2 f0 = __bfloat1622float2(h0);
    float2 f1 = __bfloat1622float2(h1);
    __nv_bfloat162 l0 = __floats2bfloat162_rn(v.x - f0.x, v.y - f0.y);
    __nv_bfloat162 l1 = __floats2bfloat162_rn(v.z - f1.x, v.w - f1.y);
    *(__nv_bfloat162*)(Hd)     = h0;
    *(__nv_bfloat162*)(Hd + 2) = h1;
    *(__nv_bfloat162*)(Ld)     = l0;
    *(__nv_bfloat162*)(Ld + 2) = l1;
}

__device__ __forceinline__ unsigned enc_f(float f) {
    unsigned u = __float_as_uint(f);
    return (u & 0x80000000u) ? ~u : (u | 0x80000000u);
}
__device__ __forceinline__ float dec_f(unsigned v) {
    return __uint_as_float((v & 0x80000000u) ? (v ^ 0x80000000u) : ~v);
}

// ---------------- fp32 -> bf16 h/l plane split (+optional fp32 copy) ------
__global__ void __launch_bounds__(256) split_kernel(
    const float4* __restrict__ src,
    __nv_bfloat16* __restrict__ h, __nv_bfloat16* __restrict__ l,
    float4* __restrict__ copy, int n4)
{
    int i = (blockIdx.x * 256 + threadIdx.x) * 2;
    if (i < n4) {
        float4 v0 = src[i];
        split_store4(h + (size_t)i * 4, l + (size_t)i * 4, v0);
        if (copy) copy[i] = v0;
        if (i + 1 < n4) {
            float4 v1 = src[i + 1];
            split_store4(h + (size_t)(i + 1) * 4, l + (size_t)(i + 1) * 4, v1);
            if (copy) copy[i + 1] = v1;
        }
    }
}

// ============ bf16-plane 3x GEMM with cp.async multistage pipeline ========
// A:[M,K] (h/l planes), B:[K,N] (h/l planes), all row-major bf16.
// mode bits: 1=relu(+bias), 2=residual(+bias), 4=write fp32 C,
//            8=write h+l planes, 32=also write fp32 C2.
// mode==4 exactly -> direct wmma store.
template<int BM, int BN, int WM, int WN, int S>
__global__ void __launch_bounds__(WM * WN * 32) bf16_gemm(
    const __nv_bfloat16* __restrict__ Ah, const __nv_bfloat16* __restrict__ Al,
    const __nv_bfloat16* __restrict__ Bh, const __nv_bfloat16* __restrict__ Bl,
    float* __restrict__ C, float* __restrict__ C2,
    __nv_bfloat16* __restrict__ Ch, __nv_bfloat16* __restrict__ Cl,
    int M, int N, int K, long long strideA, long long strideC,
    const float* __restrict__ bias, const float* __restrict__ R, int mode)
{
    constexpr int TH = WM * WN * 32;
    constexpr int BK = 32;
    constexpr int AP = 40;
    constexpr int BP = BN + 8;
    constexpr int ABYT = BM * AP * 2;
    constexpr int BBYT = BK * BP * 2;
    constexpr int STG = 2 * ABYT + 2 * BBYT;
    constexpr int MF = BM / (WM * 16);
    constexpr int NF = BN / (WN * 16);
    constexpr int AIT = BM * (BK / 8) / TH;
    constexpr int BIT = BK * (BN / 8) / TH;

    extern __shared__ char sm[];
    const int tid = threadIdx.x, w = tid >> 5;
    Ah += (size_t)blockIdx.z * strideA;
    Al += (size_t)blockIdx.z * strideA;
    if (C) C += (size_t)blockIdx.z * strideC;
    const int bm = blockIdx.y * BM;
    const int bn = blockIdx.x * BN;
    const int wm0 = (w % WM) * (MF * 16);
    const int wn0 = (w / WM) * (NF * 16);
    const int KT = K / BK;

    auto issue = [&](int tile) {
        const int k0 = tile * BK;
        char* st = sm + (tile % S) * STG;
        __nv_bfloat16* sAh = (__nv_bfloat16*)st;
        __nv_bfloat16* sAl = (__nv_bfloat16*)(st + ABYT);
        __nv_bfloat16* sBh = (__nv_bfloat16*)(st + 2 * ABYT);
        __nv_bfloat16* sBl = (__nv_bfloat16*)(st + 2 * ABYT + BBYT);
#pragma unroll
        for (int p = 0; p < AIT; p++) {
            const int c = tid + p * TH;
            const int r = c >> 2, c8 = (c & 3) * 8;
            cp16(sAh + r * AP + c8, Ah + (size_t)(bm + r) * K + k0 + c8);
            cp16(sAl + r * AP + c8, Al + (size_t)(bm + r) * K + k0 + c8);
        }
#pragma unroll
        for (int p = 0; p < BIT; p++) {
            const int c = tid + p * TH;
            const int r = c / (BN / 8), c8 = (c % (BN / 8)) * 8;
            cp16(sBh + r * BP + c8, Bh + (size_t)(k0 + r) * N + bn + c8);
            cp16(sBl + r * BP + c8, Bl + (size_t)(k0 + r) * N + bn + c8);
        }
    };

    wmma::fragment<wmma::accumulator, 16, 16, 16, float> acc[MF][NF];
#pragma unroll
    for (int i = 0; i < MF; i++)
#pragma unroll
        for (int j = 0; j < NF; j++) wmma::fill_fragment(acc[i][j], 0.f);

#pragma unroll
    for (int t = 0; t < S - 1; t++) {
        if (t < KT) issue(t);
        cp_commit();
    }

#pragma unroll 1
    for (int kt = 0; kt < KT; kt++) {
        cp_wait<S - 2>();
        __syncthreads();
        if (kt + S - 1 < KT) issue(kt + S - 1);
        cp_commit();

        char* st = sm + (kt % S) * STG;
        const __nv_bfloat16* sAh = (const __nv_bfloat16*)st;
        const __nv_bfloat16* sAl = (const __nv_bfloat16*)(st + ABYT);
        const __nv_bfloat16* sBh = (const __nv_bfloat16*)(st + 2 * ABYT);
        const __nv_bfloat16* sBl = (const __nv_bfloat16*)(st + 2 * ABYT + BBYT);

#pragma unroll
        for (int kks = 0; kks < 2; kks++) {
            const int kk = kks * 16;
            wmma::fragment<wmma::matrix_a, 16, 16, 16, __nv_bfloat16, wmma::row_major> fAh[MF];
            wmma::fragment<wmma::matrix_b, 16, 16, 16, __nv_bfloat16, wmma::row_major> fBh[NF];
#pragma unroll
            for (int i = 0; i < MF; i++)
                wmma::load_matrix_sync(fAh[i], sAh + (wm0 + i * 16) * AP + kk, AP);
#pragma unroll
            for (int j = 0; j < NF; j++)
                wmma::load_matrix_sync(fBh[j], sBh + kk * BP + wn0 + j * 16, BP);
#pragma unroll
            for (int i = 0; i < MF; i++)
#pragma unroll
                for (int j = 0; j < NF; j++)
                    wmma::mma_sync(acc[i][j], fAh[i], fBh[j], acc[i][j]);
            {
                wmma::fragment<wmma::matrix_b, 16, 16, 16, __nv_bfloat16, wmma::row_major> fBl[NF];
#pragma unroll
                for (int j = 0; j < NF; j++)
                    wmma::load_matrix_sync(fBl[j], sBl + kk * BP + wn0 + j * 16, BP);
#pragma unroll
                for (int i = 0; i < MF; i++)
#pragma unroll
                    for (int j = 0; j < NF; j++)
                        wmma::mma_sync(acc[i][j], fAh[i], fBl[j], acc[i][j]);
            }
            {
                wmma::fragment<wmma::matrix_a, 16, 16, 16, __nv_bfloat16, wmma::row_major> fAl[MF];
#pragma unroll
                for (int i = 0; i < MF; i++)
                    wmma::load_matrix_sync(fAl[i], sAl + (wm0 + i * 16) * AP + kk, AP);
#pragma unroll
                for (int i = 0; i < MF; i++)
#pragma unroll
                    for (int j = 0; j < NF; j++)
                        wmma::mma_sync(acc[i][j], fAl[i], fBh[j], acc[i][j]);
            }
        }
    }

    if (mode == 4) {
#pragma unroll
        for (int i = 0; i < MF; i++)
#pragma unroll
            for (int j = 0; j < NF; j++)
                wmma::store_matrix_sync(
                    &C[(size_t)(bm + wm0 + i * 16) * N + bn + wn0 + j * 16],
                    acc[i][j], N, wmma::mem_row_major);
        return;
    }

    __syncthreads();
    float* cs = (float*)sm;
#pragma unroll
    for (int i = 0; i < MF; i++)
#pragma unroll
        for (int j = 0; j < NF; j++)
            wmma::store_matrix_sync(cs + (size_t)(wm0 + i * 16) * BN + wn0 + j * 16,
                                    acc[i][j], BN, wmma::mem_row_major);
    __syncthreads();

    constexpr int CIT = BM * BN / 4 / TH;
#pragma unroll
    for (int p = 0; p < CIT; p++) {
        const int id = tid + p * TH;
        const int row = id / (BN / 4), c4 = id % (BN / 4);
        float4 v = ((const float4*)cs)[id];
        const int gr = bm + row;
        const int gc = bn + c4 * 4;
        if (mode & 3) {
            const float bv = bias[gr];
            v.x += bv; v.y += bv; v.z += bv; v.w += bv;
        }
        if (mode & 1) {
            v.x = fmaxf(v.x, 0.f); v.y = fmaxf(v.y, 0.f);
            v.z = fmaxf(v.z, 0.f); v.w = fmaxf(v.w, 0.f);
        }
        if (mode & 2) {
            float4 r4 = *(const float4*)&R[(size_t)gr * N + gc];
            v.x += r4.x; v.y += r4.y; v.z += r4.z; v.w += r4.w;
        }
        if (mode & 4)  *(float4*)&C[(size_t)gr * N + gc] = v;
        if (mode & 32) *(float4*)&C2[(size_t)gr * N + gc] = v;
        if (mode & 8)  split_store4(Ch + (size_t)gr * N + gc,
                                    Cl + (size_t)gr * N + gc, v);
    }
}

// ====== fused gram + argmax + scatter (bf16 planes, 3-product) =============
#define CAND 96
__global__ void __launch_bounds__(256) gram_argmax_scatter(
    const __nv_bfloat16* __restrict__ KXh, const __nv_bfloat16* __restrict__ KXl,
    const float* __restrict__ Y, float* __restrict__ attn)
{
    constexpr int AP = 72, BP = 136, CP = 132;
    extern __shared__ char sm[];
    __nv_bfloat16* aH = (__nv_bfloat16*)sm;                 // 9216
    __nv_bfloat16* aL = (__nv_bfloat16*)(sm + 9216);        // 9216
    // B stages at 18432 .. 88064 (2 stages x (bH 17408 + bL 17408))
    float*    Cs   = (float*)(sm + 88064);                  // 33792
    unsigned* rm   = (unsigned*)(sm + 121856);
    int*      cnt  = (int*)(sm + 122112);
    float*    wrow = (float*)(sm + 122368);
    int*      cm   = (int*)(sm + 122624);                   // 24576
    float*    csv  = (float*)(sm + 147200);                 // 24576 -> 171776

    const int h  = blockIdx.y;
    const int r0 = blockIdx.x * 64;
    const __nv_bfloat16* Ahg = KXh + (size_t)h * Qc * Nc;
    const __nv_bfloat16* Alg = KXl + (size_t)h * Qc * Nc;
    const int tid = threadIdx.x, w = tid >> 5, lane = tid & 31;
    const int wm0 = (w & 1) * 32, wn0 = (w >> 1) * 32;

    if (tid < 64) { rm[tid] = enc_f(-1e30f); cnt[tid] = 0; }

    auto issueB = [&](int mt, int s) {
        const int m0 = mt * 128;
        __nv_bfloat16* bH = (__nv_bfloat16*)(sm + 18432 + s * 34816);
        __nv_bfloat16* bL = (__nv_bfloat16*)(sm + 18432 + s * 34816 + 17408);
#pragma unroll
        for (int p = 0; p < 4; p++) {
            const int c = tid + p * 256;
            const int q = c >> 4, c8 = (c & 15) * 8;
            cp16(bH + q * BP + c8, Ahg + (size_t)q * Nc + m0 + c8);
            cp16(bL + q * BP + c8, Alg + (size_t)q * Nc + m0 + c8);
        }
    };

#pragma unroll
    for (int p = 0; p < 2; p++) {
        const int c = tid + p * 256;
        const int q = c >> 3, c8 = (c & 7) * 8;
        cp16(aH + q * AP + c8, Ahg + (size_t)q * Nc + r0 + c8);
        cp16(aL + q * AP + c8, Alg + (size_t)q * Nc + r0 + c8);
    }
    issueB(0, 0);
    cp_commit();

    for (int mt = 0; mt < Nc / 128; mt++) {
        if (mt + 1 < Nc / 128) issueB(mt + 1, (mt + 1) & 1);
        cp_commit();
        cp_wait<1>();
        __syncthreads();

        const __nv_bfloat16* bH = (const __nv_bfloat16*)(sm + 18432 + (mt & 1) * 34816);
        const __nv_bfloat16* bL = (const __nv_bfloat16*)(sm + 18432 + (mt & 1) * 34816 + 17408);

        wmma::fragment<wmma::accumulator, 16, 16, 16, float> acc[2][2];
#pragma unroll
        for (int i = 0; i < 2; i++)
#pragma unroll
            for (int j = 0; j < 2; j++) wmma::fill_fragment(acc[i][j], 0.f);

#pragma unroll
        for (int kks = 0; kks < 4; kks++) {
            const int kk = kks * 16;
            wmma::fragment<wmma::matrix_a, 16, 16, 16, __nv_bfloat16, wmma::col_major> fAh[2];
            wmma::fragment<wmma::matrix_b, 16, 16, 16, __nv_bfloat16, wmma::row_major> fBh[2];
#pragma unroll
            for (int i = 0; i < 2; i++)
                wmma::load_matrix_sync(fAh[i], aH + kk * AP + wm0 + i * 16, AP);
#pragma unroll
            for (int j = 0; j < 2; j++)
                wmma::load_matrix_sync(fBh[j], bH + kk * BP + wn0 + j * 16, BP);
#pragma unroll
            for (int i = 0; i < 2; i++)
#pragma unroll
                for (int j = 0; j < 2; j++)
                    wmma::mma_sync(acc[i][j], fAh[i], fBh[j], acc[i][j]);
            {
                wmma::fragment<wmma::matrix_b, 16, 16, 16, __nv_bfloat16, wmma::row_major> fBl[2];
#pragma unroll
                for (int j = 0; j < 2; j++)
                    wmma::load_matrix_sync(fBl[j], bL + kk * BP + wn0 + j * 16, BP);
#pragma unroll
                for (int i = 0; i < 2; i++)
#pragma unroll
                    for (int j = 0; j < 2; j++)
                        wmma::mma_sync(acc[i][j], fAh[i], fBl[j], acc[i][j]);
            }
            {
                wmma::fragment<wmma::matrix_a, 16, 16, 16, __nv_bfloat16, wmma::col_major> fAl[2];
#pragma unroll
                for (int i = 0; i < 2; i++)
                    wmma::load_matrix_sync(fAl[i], aL + kk * AP + wm0 + i * 16, AP);
#pragma unroll
                for (int i = 0; i < 2; i++)
#pragma unroll
                    for (int j = 0; j < 2; j++)
                        wmma::mma_sync(acc[i][j], fAl[i], fBh[j], acc[i][j]);
            }
        }
#pragma unroll
        for (int i = 0; i < 2; i++)
#pragma unroll
            for (int j = 0; j < 2; j++)
                wmma::store_matrix_sync(Cs + (wm0 + i * 16) * CP + wn0 + j * 16,
                                        acc[i][j], CP, wmma::mem_row_major);
        __syncthreads();

        const int r = tid >> 2;
        const int c0 = (tid & 3) * 32;
        float tm = -1e30f;
#pragma unroll
        for (int c = 0; c < 32; c++) tm = fmaxf(tm, Cs[r * CP + c0 + c]);
        tm = fmaxf(tm, __shfl_xor_sync(0xffffffffu, tm, 1, 4));
        tm = fmaxf(tm, __shfl_xor_sync(0xffffffffu, tm, 2, 4));
        if ((tid & 3) == 0) atomicMax(&rm[r], enc_f(tm));
        __syncthreads();

        const float thr = dec_f(rm[r]) - 0.5f;
        const int m0 = mt * 128;
#pragma unroll
        for (int c = 0; c < 32; c++) {
            const float v = Cs[r * CP + c0 + c];
            if (v >= thr) {
                int pos = atomicAdd(&cnt[r], 1);
                if (pos < CAND) {
                    cm[r * CAND + pos]  = m0 + c0 + c;
                    csv[r * CAND + pos] = v;
                }
            }
        }
        __syncthreads();
    }

    if (tid < 64) {
        const float fmax = dec_f(rm[tid]);
        const float thrF = fmax - 0.5f;
        const int nc = cnt[tid] < CAND ? cnt[tid] : CAND;
        int hits = 0;
        for (int j = 0; j < nc; j++) {
            if (csv[tid * CAND + j] >= thrF) {
                cm[tid * CAND + hits] = cm[tid * CAND + j];
                hits++;
            }
        }
        cnt[tid] = hits;
        wrow[tid] = (fabsf(fmax) > 0.5f && hits > 0) ? 1.f / (float)hits : 0.f;
    }
    __syncthreads();

    const float* Yh = Y + (size_t)h * Dc * Nc;
    for (int rr = 0; rr < 8; rr++) {
        const int r = w * 8 + rr;
        const float wv = wrow[r];
        const int hits = cnt[r];
        if (wv == 0.f || hits == 0) continue;
        const int n = r0 + r;
        float yv[16];
#pragma unroll
        for (int p = 0; p < 16; p++)
            yv[p] = wv * Yh[(size_t)(lane + p * 32) * Nc + n];
        for (int j = 0; j < hits; j++) {
            const int m = cm[r * CAND + j];
#pragma unroll
            for (int p = 0; p < 16; p++)
                atomicAdd(&attn[(size_t)(lane + p * 32) * Nc + m], yv[p]);
        }
    }
}

// --------------------------------------------------------------------------
extern "C" void kernel_launch(void* const* d_in, const int* in_sizes, int n_in,
                              void* d_out, int out_size)
{
    const float* X  = (const float*)d_in[0];
    const float* Kp = (const float*)d_in[1];
    const float* Vp = (const float*)d_in[2];
    const float* W1 = (const float*)d_in[3];
    const float* b1 = (const float*)d_in[4];
    const float* W2 = (const float*)d_in[5];
    const float* b2 = (const float*)d_in[6];

    float *gX, *gAttn, *gY;
    __nv_bfloat16 *gKh, *gKl, *gVh, *gVl, *gW1h, *gW1l, *gW2h, *gW2l;
    __nv_bfloat16 *gXh, *gXl, *gAth, *gAtl, *gF1h, *gF1l, *gKXh, *gKXl;
    cudaGetSymbolAddress((void**)&gX,   g_X);
    cudaGetSymbolAddress((void**)&gAttn,g_attn);
    cudaGetSymbolAddress((void**)&gY,   g_Y);
    cudaGetSymbolAddress((void**)&gKh,  g_Kh);   cudaGetSymbolAddress((void**)&gKl,  g_Kl);
    cudaGetSymbolAddress((void**)&gVh,  g_Vh);   cudaGetSymbolAddress((void**)&gVl,  g_Vl);
    cudaGetSymbolAddress((void**)&gW1h, g_W1h);  cudaGetSymbolAddress((void**)&gW1l, g_W1l);
    cudaGetSymbolAddress((void**)&gW2h, g_W2h);  cudaGetSymbolAddress((void**)&gW2l, g_W2l);
    cudaGetSymbolAddress((void**)&gXh,  g_Xh);   cudaGetSymbolAddress((void**)&gXl,  g_Xl);
    cudaGetSymbolAddress((void**)&gAth, g_Ath);  cudaGetSymbolAddress((void**)&gAtl, g_Atl);
    cudaGetSymbolAddress((void**)&gF1h, g_F1h);  cudaGetSymbolAddress((void**)&gF1l, g_F1l);
    cudaGetSymbolAddress((void**)&gKXh, g_KXh);  cudaGetSymbolAddress((void**)&gKXl, g_KXl);

    const int SMY  = 4 * (2 * 128 * 40 * 2 + 2 * 32 * 264 * 2);   // 217088
    const int SMF2 = 4 * (2 *  64 * 40 * 2 + 2 * 32 * 136 * 2);   // 110592
    const int SMKX = 4 * (2 *  64 * 40 * 2 + 2 * 32 *  72 * 2);   // 77824
    const int SMGR = 171776;
    cudaFuncSetAttribute(bf16_gemm<128, 256, 2, 4, 4>,
                         cudaFuncAttributeMaxDynamicSharedMemorySize, SMY);
    cudaFuncSetAttribute(bf16_gemm<64, 128, 2, 4, 4>,
                         cudaFuncAttributeMaxDynamicSharedMemorySize, SMF2);
    cudaFuncSetAttribute(bf16_gemm<64, 64, 2, 2, 4>,
                         cudaFuncAttributeMaxDynamicSharedMemorySize, SMKX);
    cudaFuncSetAttribute(gram_argmax_scatter,
                         cudaFuncAttributeMaxDynamicSharedMemorySize, SMGR);

    {
        const int nK  = Lc * Hc * Qc * Dc / 4;
        const int nV  = Lc * Hc * Dc * Dc / 4;
        const int nW  = Lc * DFFc * Dc / 4;
        const int nX  = Dc * Nc / 4;
        split_kernel<<<(nK / 2 + 255) / 256, 256>>>((const float4*)Kp, gKh, gKl, nullptr, nK);
        split_kernel<<<(nV / 2 + 255) / 256, 256>>>((const float4*)Vp, gVh, gVl, nullptr, nV);
        split_kernel<<<(nW / 2 + 255) / 256, 256>>>((const float4*)W1, gW1h, gW1l, nullptr, nW);
        split_kernel<<<(nW / 2 + 255) / 256, 256>>>((const float4*)W2, gW2h, gW2l, nullptr, nW);
        // X split also seeds attn = X for layer 0 (no memcpy needed)
        split_kernel<<<(nX / 2 + 255) / 256, 256>>>((const float4*)X,  gXh,  gXl,
                                                    (float4*)gAttn, nX);
    }

    for (int l = 0; l < Lc; l++) {
        const float* b1l = b1 + (size_t)l * DFFc;
        const float* b2l = b2 + (size_t)l * Dc;

        // 1) KX planes = K_l @ X  (mode 8)
        bf16_gemm<64, 64, 2, 2, 4><<<dim3(Nc / 64, (Hc * Qc) / 64, 1), 128, SMKX>>>(
            gKh + (size_t)l * Hc * Qc * Dc, gKl + (size_t)l * Hc * Qc * Dc,
            gXh, gXl, nullptr, nullptr, gKXh, gKXl,
            Hc * Qc, Nc, Dc, 0, 0, nullptr, nullptr, 8);

        // 2) Y[h] = V_lh @ X  (mode 4, 128 blocks)
        bf16_gemm<128, 256, 2, 4, 4><<<dim3(Nc / 256, Dc / 128, Hc), 256, SMY>>>(
            gVh + (size_t)l * Hc * Dc * Dc, gVl + (size_t)l * Hc * Dc * Dc,
            gXh, gXl, gY, nullptr, nullptr, nullptr,
            Dc, Nc, Dc, (long long)Dc * Dc, (long long)Dc * Nc,
            nullptr, nullptr, 4);

        // 3) fused gram+argmax+scatter: attn (already = X) += scatter
        gram_argmax_scatter<<<dim3(Nc / 64, Hc), 256, SMGR>>>(gKXh, gKXl, gY, gAttn);

        // 4) attn planes
        split_kernel<<<(Dc * Nc / 8 + 255) / 256, 256>>>(
            (const float4*)gAttn, gAth, gAtl, nullptr, Dc * Nc / 4);

        // 5) ff1 planes = relu(W1_l @ attn + b1)  (mode 9)
        bf16_gemm<128, 256, 2, 4, 4><<<dim3(Nc / 256, DFFc / 128, 1), 256, SMY>>>(
            gW1h + (size_t)l * DFFc * Dc, gW1l + (size_t)l * DFFc * Dc,
            gAth, gAtl, nullptr, nullptr, gF1h, gF1l,
            DFFc, Nc, Dc, 0, 0, b1l, nullptr, 9);

        // 6) X = attn + W2_l @ ff1 + b2  (mode 46 = res|fp32|planes|copy->attn)
        bf16_gemm<64, 128, 2, 4, 4><<<dim3(Nc / 128, Dc / 64, 1), 256, SMF2>>>(
            gW2h + (size_t)l * Dc * DFFc, gW2l + (size_t)l * Dc * DFFc,
            gF1h, gF1l, gX, gAttn, gXh, gXl,
            Dc, Nc, DFFc, 0, 0, b2l, gAttn, 46);
    }

    cudaMemcpyAsync(d_out, gX, (size_t)Dc * Nc * sizeof(float),
                    cudaMemcpyDeviceToDevice);
}

// round 10
// speedup vs baseline: 1.0051x; 1.0051x over previous
#include <cuda_runtime.h>
#include <cuda_bf16.h>
#include <mma.h>
#include <cstdint>

using namespace nvcuda;

#define Lc   8
#define Hc   4
#define Qc   64
#define Dc   512
#define Nc   2048
#define DFFc 2048

// ---------------- device scratch (no allocations allowed) ----------------
__device__ float g_X[Dc * Nc];
__device__ float g_attn[Dc * Nc];
__device__ float g_Y[Hc * Dc * Nc];
__device__ __nv_bfloat16 g_Kh[Lc * Hc * Qc * Dc],  g_Kl[Lc * Hc * Qc * Dc];
__device__ __nv_bfloat16 g_Vh[Lc * Hc * Dc * Dc],  g_Vl[Lc * Hc * Dc * Dc];
__device__ __nv_bfloat16 g_W1h[Lc * DFFc * Dc],    g_W1l[Lc * DFFc * Dc];
__device__ __nv_bfloat16 g_W2h[Lc * Dc * DFFc],    g_W2l[Lc * Dc * DFFc];
__device__ __nv_bfloat16 g_Xh[Dc * Nc],            g_Xl[Dc * Nc];
__device__ __nv_bfloat16 g_Ath[Dc * Nc],           g_Atl[Dc * Nc];
__device__ __nv_bfloat16 g_F1h[DFFc * Nc],         g_F1l[DFFc * Nc];
__device__ __nv_bfloat16 g_KXh[Hc * Qc * Nc],      g_KXl[Hc * Qc * Nc];

// ---------------- helpers --------------------------------------------------
__device__ __forceinline__ uint32_t smem_u32(const void* p) {
    uint32_t a;
    asm("{ .reg .u64 t; cvta.to.shared.u64 t, %1; cvt.u32.u64 %0, t; }"
        : "=r"(a) : "l"(p));
    return a;
}
__device__ __forceinline__ void cp16(void* s, const void* g) {
    asm volatile("cp.async.cg.shared.global [%0], [%1], 16;"
                 :: "r"(smem_u32(s)), "l"(g) : "memory");
}
__device__ __forceinline__ void cp_commit() {
    asm volatile("cp.async.commit_group;" ::: "memory");
}
template<int N> __device__ __forceinline__ void cp_wait() {
    asm volatile("cp.async.wait_group %0;" :: "n"(N) : "memory");
}

__device__ __forceinline__ void split_store4(__nv_bfloat16* __restrict__ Hd,
                                             __nv_bfloat16* __restrict__ Ld,
                                             float4 v)
{
    __nv_bfloat162 h0 = __floats2bfloat162_rn(v.x, v.y);
    __nv_bfloat162 h1 = __floats2bfloat162_rn(v.z, v.w);
    float2 f0 = __bfloat1622float2(h0);
    float2 f1 = __bfloat1622float2(h1);
    __nv_bfloat162 l0 = __floats2bfloat162_rn(v.x - f0.x, v.y - f0.y);
    __nv_bfloat162 l1 = __floats2bfloat162_rn(v.z - f1.x, v.w - f1.y);
    *(__nv_bfloat162*)(Hd)     = h0;
    *(__nv_bfloat162*)(Hd + 2) = h1;
    *(__nv_bfloat162*)(Ld)     = l0;
    *(__nv_bfloat162*)(Ld + 2) = l1;
}

__device__ __forceinline__ unsigned enc_f(float f) {
    unsigned u = __float_as_uint(f);
    return (u & 0x80000000u) ? ~u : (u | 0x80000000u);
}
__device__ __forceinline__ float dec_f(unsigned v) {
    return __uint_as_float((v & 0x80000000u) ? (v ^ 0x80000000u) : ~v);
}

// ---------------- fp32 -> bf16 h/l plane split (+optional fp32 copy) ------
// R8-proven access pattern: 1 float4 per thread.
__global__ void __launch_bounds__(256) split_kernel(
    const float4* __restrict__ src,
    __nv_bfloat16* __restrict__ h, __nv_bfloat16* __restrict__ l,
    float4* __restrict__ copy, int n4)
{
    int i = blockIdx.x * 256 + threadIdx.x;
    if (i < n4) {
        float4 v = src[i];
        split_store4(h + (size_t)i * 4, l + (size_t)i * 4, v);
        if (copy) copy[i] = v;
    }
}

// ============ bf16-plane 3x GEMM with cp.async multistage pipeline ========
// A:[M,K] (h/l planes), B:[K,N] (h/l planes), all row-major bf16.
// mode bits: 1=relu(+bias), 2=residual(+bias), 4=write fp32 C,
//            8=write h+l planes, 32=also write fp32 C2.
// mode==4 exactly -> direct wmma store.
template<int BM, int BN, int WM, int WN, int S>
__global__ void __launch_bounds__(WM * WN * 32) bf16_gemm(
    const __nv_bfloat16* __restrict__ Ah, const __nv_bfloat16* __restrict__ Al,
    const __nv_bfloat16* __restrict__ Bh, const __nv_bfloat16* __restrict__ Bl,
    float* __restrict__ C, float* __restrict__ C2,
    __nv_bfloat16* __restrict__ Ch, __nv_bfloat16* __restrict__ Cl,
    int M, int N, int K, long long strideA, long long strideC,
    const float* __restrict__ bias, const float* __restrict__ R, int mode)
{
    constexpr int TH = WM * WN * 32;
    constexpr int BK = 32;
    constexpr int AP = 40;
    constexpr int BP = BN + 8;
    constexpr int ABYT = BM * AP * 2;
    constexpr int BBYT = BK * BP * 2;
    constexpr int STG = 2 * ABYT + 2 * BBYT;
    constexpr int MF = BM / (WM * 16);
    constexpr int NF = BN / (WN * 16);
    constexpr int AIT = BM * (BK / 8) / TH;
    constexpr int BIT = BK * (BN / 8) / TH;

    extern __shared__ char sm[];
    const int tid = threadIdx.x, w = tid >> 5;
    Ah += (size_t)blockIdx.z * strideA;
    Al += (size_t)blockIdx.z * strideA;
    if (C) C += (size_t)blockIdx.z * strideC;
    const int bm = blockIdx.y * BM;
    const int bn = blockIdx.x * BN;
    const int wm0 = (w % WM) * (MF * 16);
    const int wn0 = (w / WM) * (NF * 16);
    const int KT = K / BK;

    auto issue = [&](int tile) {
        const int k0 = tile * BK;
        char* st = sm + (tile % S) * STG;
        __nv_bfloat16* sAh = (__nv_bfloat16*)st;
        __nv_bfloat16* sAl = (__nv_bfloat16*)(st + ABYT);
        __nv_bfloat16* sBh = (__nv_bfloat16*)(st + 2 * ABYT);
        __nv_bfloat16* sBl = (__nv_bfloat16*)(st + 2 * ABYT + BBYT);
#pragma unroll
        for (int p = 0; p < AIT; p++) {
            const int c = tid + p * TH;
            const int r = c >> 2, c8 = (c & 3) * 8;
            cp16(sAh + r * AP + c8, Ah + (size_t)(bm + r) * K + k0 + c8);
            cp16(sAl + r * AP + c8, Al + (size_t)(bm + r) * K + k0 + c8);
        }
#pragma unroll
        for (int p = 0; p < BIT; p++) {
            const int c = tid + p * TH;
            const int r = c / (BN / 8), c8 = (c % (BN / 8)) * 8;
            cp16(sBh + r * BP + c8, Bh + (size_t)(k0 + r) * N + bn + c8);
            cp16(sBl + r * BP + c8, Bl + (size_t)(k0 + r) * N + bn + c8);
        }
    };

    wmma::fragment<wmma::accumulator, 16, 16, 16, float> acc[MF][NF];
#pragma unroll
    for (int i = 0; i < MF; i++)
#pragma unroll
        for (int j = 0; j < NF; j++) wmma::fill_fragment(acc[i][j], 0.f);

#pragma unroll
    for (int t = 0; t < S - 1; t++) {
        if (t < KT) issue(t);
        cp_commit();
    }

#pragma unroll 1
    for (int kt = 0; kt < KT; kt++) {
        cp_wait<S - 2>();
        __syncthreads();
        if (kt + S - 1 < KT) issue(kt + S - 1);
        cp_commit();

        char* st = sm + (kt % S) * STG;
        const __nv_bfloat16* sAh = (const __nv_bfloat16*)st;
        const __nv_bfloat16* sAl = (const __nv_bfloat16*)(st + ABYT);
        const __nv_bfloat16* sBh = (const __nv_bfloat16*)(st + 2 * ABYT);
        const __nv_bfloat16* sBl = (const __nv_bfloat16*)(st + 2 * ABYT + BBYT);

#pragma unroll
        for (int kks = 0; kks < 2; kks++) {
            const int kk = kks * 16;
            wmma::fragment<wmma::matrix_a, 16, 16, 16, __nv_bfloat16, wmma::row_major> fAh[MF];
            wmma::fragment<wmma::matrix_b, 16, 16, 16, __nv_bfloat16, wmma::row_major> fBh[NF];
#pragma unroll
            for (int i = 0; i < MF; i++)
                wmma::load_matrix_sync(fAh[i], sAh + (wm0 + i * 16) * AP + kk, AP);
#pragma unroll
            for (int j = 0; j < NF; j++)
                wmma::load_matrix_sync(fBh[j], sBh + kk * BP + wn0 + j * 16, BP);
#pragma unroll
            for (int i = 0; i < MF; i++)
#pragma unroll
                for (int j = 0; j < NF; j++)
                    wmma::mma_sync(acc[i][j], fAh[i], fBh[j], acc[i][j]);
            {
                wmma::fragment<wmma::matrix_b, 16, 16, 16, __nv_bfloat16, wmma::row_major> fBl[NF];
#pragma unroll
                for (int j = 0; j < NF; j++)
                    wmma::load_matrix_sync(fBl[j], sBl + kk * BP + wn0 + j * 16, BP);
#pragma unroll
                for (int i = 0; i < MF; i++)
#pragma unroll
                    for (int j = 0; j < NF; j++)
                        wmma::mma_sync(acc[i][j], fAh[i], fBl[j], acc[i][j]);
            }
            {
                wmma::fragment<wmma::matrix_a, 16, 16, 16, __nv_bfloat16, wmma::row_major> fAl[MF];
#pragma unroll
                for (int i = 0; i < MF; i++)
                    wmma::load_matrix_sync(fAl[i], sAl + (wm0 + i * 16) * AP + kk, AP);
#pragma unroll
                for (int i = 0; i < MF; i++)
#pragma unroll
                    for (int j = 0; j < NF; j++)
                        wmma::mma_sync(acc[i][j], fAl[i], fBh[j], acc[i][j]);
            }
        }
    }

    if (mode == 4) {
#pragma unroll
        for (int i = 0; i < MF; i++)
#pragma unroll
            for (int j = 0; j < NF; j++)
                wmma::store_matrix_sync(
                    &C[(size_t)(bm + wm0 + i * 16) * N + bn + wn0 + j * 16],
                    acc[i][j], N, wmma::mem_row_major);
        return;
    }

    __syncthreads();
    float* cs = (float*)sm;
#pragma unroll
    for (int i = 0; i < MF; i++)
#pragma unroll
        for (int j = 0; j < NF; j++)
            wmma::store_matrix_sync(cs + (size_t)(wm0 + i * 16) * BN + wn0 + j * 16,
                                    acc[i][j], BN, wmma::mem_row_major);
    __syncthreads();

    constexpr int CIT = BM * BN / 4 / TH;
#pragma unroll
    for (int p = 0; p < CIT; p++) {
        const int id = tid + p * TH;
        const int row = id / (BN / 4), c4 = id % (BN / 4);
        float4 v = ((const float4*)cs)[id];
        const int gr = bm + row;
        const int gc = bn + c4 * 4;
        if (mode & 3) {
            const float bv = bias[gr];
            v.x += bv; v.y += bv; v.z += bv; v.w += bv;
        }
        if (mode & 1) {
            v.x = fmaxf(v.x, 0.f); v.y = fmaxf(v.y, 0.f);
            v.z = fmaxf(v.z, 0.f); v.w = fmaxf(v.w, 0.f);
        }
        if (mode & 2) {
            float4 r4 = *(const float4*)&R[(size_t)gr * N + gc];
            v.x += r4.x; v.y += r4.y; v.z += r4.z; v.w += r4.w;
        }
        if (mode & 4)  *(float4*)&C[(size_t)gr * N + gc] = v;
        if (mode & 32) *(float4*)&C2[(size_t)gr * N + gc] = v;
        if (mode & 8)  split_store4(Ch + (size_t)gr * N + gc,
                                    Cl + (size_t)gr * N + gc, v);
    }
}

// ====== fused gram + argmax + scatter (bf16 planes, 3-product) =============
#define CAND 96
__global__ void __launch_bounds__(256) gram_argmax_scatter(
    const __nv_bfloat16* __restrict__ KXh, const __nv_bfloat16* __restrict__ KXl,
    const float* __restrict__ Y, float* __restrict__ attn)
{
    constexpr int AP = 72, BP = 136, CP = 132;
    extern __shared__ char sm[];
    __nv_bfloat16* aH = (__nv_bfloat16*)sm;                 // 9216
    __nv_bfloat16* aL = (__nv_bfloat16*)(sm + 9216);        // 9216
    float*    Cs   = (float*)(sm + 88064);                  // 33792
    unsigned* rm   = (unsigned*)(sm + 121856);
    int*      cnt  = (int*)(sm + 122112);
    float*    wrow = (float*)(sm + 122368);
    int*      cm   = (int*)(sm + 122624);                   // 24576
    float*    csv  = (float*)(sm + 147200);                 // 24576 -> 171776

    const int h  = blockIdx.y;
    const int r0 = blockIdx.x * 64;
    const __nv_bfloat16* Ahg = KXh + (size_t)h * Qc * Nc;
    const __nv_bfloat16* Alg = KXl + (size_t)h * Qc * Nc;
    const int tid = threadIdx.x, w = tid >> 5, lane = tid & 31;
    const int wm0 = (w & 1) * 32, wn0 = (w >> 1) * 32;

    if (tid < 64) { rm[tid] = enc_f(-1e30f); cnt[tid] = 0; }

    auto issueB = [&](int mt, int s) {
        const int m0 = mt * 128;
        __nv_bfloat16* bH = (__nv_bfloat16*)(sm + 18432 + s * 34816);
        __nv_bfloat16* bL = (__nv_bfloat16*)(sm + 18432 + s * 34816 + 17408);
#pragma unroll
        for (int p = 0; p < 4; p++) {
            const int c = tid + p * 256;
            const int q = c >> 4, c8 = (c & 15) * 8;
            cp16(bH + q * BP + c8, Ahg + (size_t)q * Nc + m0 + c8);
            cp16(bL + q * BP + c8, Alg + (size_t)q * Nc + m0 + c8);
        }
    };

#pragma unroll
    for (int p = 0; p < 2; p++) {
        const int c = tid + p * 256;
        const int q = c >> 3, c8 = (c & 7) * 8;
        cp16(aH + q * AP + c8, Ahg + (size_t)q * Nc + r0 + c8);
        cp16(aL + q * AP + c8, Alg + (size_t)q * Nc + r0 + c8);
    }
    issueB(0, 0);
    cp_commit();

    for (int mt = 0; mt < Nc / 128; mt++) {
        if (mt + 1 < Nc / 128) issueB(mt + 1, (mt + 1) & 1);
        cp_commit();
        cp_wait<1>();
        __syncthreads();

        const __nv_bfloat16* bH = (const __nv_bfloat16*)(sm + 18432 + (mt & 1) * 34816);
        const __nv_bfloat16* bL = (const __nv_bfloat16*)(sm + 18432 + (mt & 1) * 34816 + 17408);

        wmma::fragment<wmma::accumulator, 16, 16, 16, float> acc[2][2];
#pragma unroll
        for (int i = 0; i < 2; i++)
#pragma unroll
            for (int j = 0; j < 2; j++) wmma::fill_fragment(acc[i][j], 0.f);

#pragma unroll
        for (int kks = 0; kks < 4; kks++) {
            const int kk = kks * 16;
            wmma::fragment<wmma::matrix_a, 16, 16, 16, __nv_bfloat16, wmma::col_major> fAh[2];
            wmma::fragment<wmma::matrix_b, 16, 16, 16, __nv_bfloat16, wmma::row_major> fBh[2];
#pragma unroll
            for (int i = 0; i < 2; i++)
                wmma::load_matrix_sync(fAh[i], aH + kk * AP + wm0 + i * 16, AP);
#pragma unroll
            for (int j = 0; j < 2; j++)
                wmma::load_matrix_sync(fBh[j], bH + kk * BP + wn0 + j * 16, BP);
#pragma unroll
            for (int i = 0; i < 2; i++)
#pragma unroll
                for (int j = 0; j < 2; j++)
                    wmma::mma_sync(acc[i][j], fAh[i], fBh[j], acc[i][j]);
            {
                wmma::fragment<wmma::matrix_b, 16, 16, 16, __nv_bfloat16, wmma::row_major> fBl[2];
#pragma unroll
                for (int j = 0; j < 2; j++)
                    wmma::load_matrix_sync(fBl[j], bL + kk * BP + wn0 + j * 16, BP);
#pragma unroll
                for (int i = 0; i < 2; i++)
#pragma unroll
                    for (int j = 0; j < 2; j++)
                        wmma::mma_sync(acc[i][j], fAh[i], fBl[j], acc[i][j]);
            }
            {
                wmma::fragment<wmma::matrix_a, 16, 16, 16, __nv_bfloat16, wmma::col_major> fAl[2];
#pragma unroll
                for (int i = 0; i < 2; i++)
                    wmma::load_matrix_sync(fAl[i], aL + kk * AP + wm0 + i * 16, AP);
#pragma unroll
                for (int i = 0; i < 2; i++)
#pragma unroll
                    for (int j = 0; j < 2; j++)
                        wmma::mma_sync(acc[i][j], fAl[i], fBh[j], acc[i][j]);
            }
        }
#pragma unroll
        for (int i = 0; i < 2; i++)
#pragma unroll
            for (int j = 0; j < 2; j++)
                wmma::store_matrix_sync(Cs + (wm0 + i * 16) * CP + wn0 + j * 16,
                                        acc[i][j], CP, wmma::mem_row_major);
        __syncthreads();

        const int r = tid >> 2;
        const int c0 = (tid & 3) * 32;
        float tm = -1e30f;
#pragma unroll
        for (int c = 0; c < 32; c++) tm = fmaxf(tm, Cs[r * CP + c0 + c]);
        tm = fmaxf(tm, __shfl_xor_sync(0xffffffffu, tm, 1, 4));
        tm = fmaxf(tm, __shfl_xor_sync(0xffffffffu, tm, 2, 4));
        if ((tid & 3) == 0) atomicMax(&rm[r], enc_f(tm));
        __syncthreads();

        const float thr = dec_f(rm[r]) - 0.5f;
        const int m0 = mt * 128;
#pragma unroll
        for (int c = 0; c < 32; c++) {
            const float v = Cs[r * CP + c0 + c];
            if (v >= thr) {
                int pos = atomicAdd(&cnt[r], 1);
                if (pos < CAND) {
                    cm[r * CAND + pos]  = m0 + c0 + c;
                    csv[r * CAND + pos] = v;
                }
            }
        }
        __syncthreads();
    }

    if (tid < 64) {
        const float fmax = dec_f(rm[tid]);
        const float thrF = fmax - 0.5f;
        const int nc = cnt[tid] < CAND ? cnt[tid] : CAND;
        int hits = 0;
        for (int j = 0; j < nc; j++) {
            if (csv[tid * CAND + j] >= thrF) {
                cm[tid * CAND + hits] = cm[tid * CAND + j];
                hits++;
            }
        }
        cnt[tid] = hits;
        wrow[tid] = (fabsf(fmax) > 0.5f && hits > 0) ? 1.f / (float)hits : 0.f;
    }
    __syncthreads();

    const float* Yh = Y + (size_t)h * Dc * Nc;
    for (int rr = 0; rr < 8; rr++) {
        const int r = w * 8 + rr;
        const float wv = wrow[r];
        const int hits = cnt[r];
        if (wv == 0.f || hits == 0) continue;
        const int n = r0 + r;
        float yv[16];
#pragma unroll
        for (int p = 0; p < 16; p++)
            yv[p] = wv * Yh[(size_t)(lane + p * 32) * Nc + n];
        for (int j = 0; j < hits; j++) {
            const int m = cm[r * CAND + j];
#pragma unroll
            for (int p = 0; p < 16; p++)
                atomicAdd(&attn[(size_t)(lane + p * 32) * Nc + m], yv[p]);
        }
    }
}

// --------------------------------------------------------------------------
extern "C" void kernel_launch(void* const* d_in, const int* in_sizes, int n_in,
                              void* d_out, int out_size)
{
    const float* X  = (const float*)d_in[0];
    const float* Kp = (const float*)d_in[1];
    const float* Vp = (const float*)d_in[2];
    const float* W1 = (const float*)d_in[3];
    const float* b1 = (const float*)d_in[4];
    const float* W2 = (const float*)d_in[5];
    const float* b2 = (const float*)d_in[6];

    float *gX, *gAttn, *gY;
    __nv_bfloat16 *gKh, *gKl, *gVh, *gVl, *gW1h, *gW1l, *gW2h, *gW2l;
    __nv_bfloat16 *gXh, *gXl, *gAth, *gAtl, *gF1h, *gF1l, *gKXh, *gKXl;
    cudaGetSymbolAddress((void**)&gX,   g_X);
    cudaGetSymbolAddress((void**)&gAttn,g_attn);
    cudaGetSymbolAddress((void**)&gY,   g_Y);
    cudaGetSymbolAddress((void**)&gKh,  g_Kh);   cudaGetSymbolAddress((void**)&gKl,  g_Kl);
    cudaGetSymbolAddress((void**)&gVh,  g_Vh);   cudaGetSymbolAddress((void**)&gVl,  g_Vl);
    cudaGetSymbolAddress((void**)&gW1h, g_W1h);  cudaGetSymbolAddress((void**)&gW1l, g_W1l);
    cudaGetSymbolAddress((void**)&gW2h, g_W2h);  cudaGetSymbolAddress((void**)&gW2l, g_W2l);
    cudaGetSymbolAddress((void**)&gXh,  g_Xh);   cudaGetSymbolAddress((void**)&gXl,  g_Xl);
    cudaGetSymbolAddress((void**)&gAth, g_Ath);  cudaGetSymbolAddress((void**)&gAtl, g_Atl);
    cudaGetSymbolAddress((void**)&gF1h, g_F1h);  cudaGetSymbolAddress((void**)&gF1l, g_F1l);
    cudaGetSymbolAddress((void**)&gKXh, g_KXh);  cudaGetSymbolAddress((void**)&gKXl, g_KXl);

    const int SMY  = 4 * (2 * 128 * 40 * 2 + 2 * 32 * 264 * 2);   // 217088
    const int SMF2 = 4 * (2 *  64 * 40 * 2 + 2 * 32 * 136 * 2);   // 110592
    const int SMKX = 4 * (2 *  64 * 40 * 2 + 2 * 32 *  72 * 2);   // 77824
    const int SMGR = 171776;
    cudaFuncSetAttribute(bf16_gemm<128, 256, 2, 4, 4>,
                         cudaFuncAttributeMaxDynamicSharedMemorySize, SMY);
    cudaFuncSetAttribute(bf16_gemm<64, 128, 2, 4, 4>,
                         cudaFuncAttributeMaxDynamicSharedMemorySize, SMF2);
    cudaFuncSetAttribute(bf16_gemm<64, 64, 2, 2, 4>,
                         cudaFuncAttributeMaxDynamicSharedMemorySize, SMKX);
    cudaFuncSetAttribute(gram_argmax_scatter,
                         cudaFuncAttributeMaxDynamicSharedMemorySize, SMGR);

    {
        const int nK  = Lc * Hc * Qc * Dc / 4;
        const int nV  = Lc * Hc * Dc * Dc / 4;
        const int nW  = Lc * DFFc * Dc / 4;
        const int nX  = Dc * Nc / 4;
        split_kernel<<<(nK + 255) / 256, 256>>>((const float4*)Kp, gKh, gKl, nullptr, nK);
        split_kernel<<<(nV + 255) / 256, 256>>>((const float4*)Vp, gVh, gVl, nullptr, nV);
        split_kernel<<<(nW + 255) / 256, 256>>>((const float4*)W1, gW1h, gW1l, nullptr, nW);
        split_kernel<<<(nW + 255) / 256, 256>>>((const float4*)W2, gW2h, gW2l, nullptr, nW);
        // X split also seeds attn = X for layer 0 (no memcpy needed)
        split_kernel<<<(nX + 255) / 256, 256>>>((const float4*)X, gXh, gXl,
                                                (float4*)gAttn, nX);
    }

    for (int l = 0; l < Lc; l++) {
        const float* b1l = b1 + (size_t)l * DFFc;
        const float* b2l = b2 + (size_t)l * Dc;
        const bool last = (l == Lc - 1);

        // 1) KX planes = K_l @ X  (mode 8)
        bf16_gemm<64, 64, 2, 2, 4><<<dim3(Nc / 64, (Hc * Qc) / 64, 1), 128, SMKX>>>(
            gKh + (size_t)l * Hc * Qc * Dc, gKl + (size_t)l * Hc * Qc * Dc,
            gXh, gXl, nullptr, nullptr, gKXh, gKXl,
            Hc * Qc, Nc, Dc, 0, 0, nullptr, nullptr, 8);

        // 2) Y[h] = V_lh @ X  (mode 4, 128 blocks)
        bf16_gemm<128, 256, 2, 4, 4><<<dim3(Nc / 256, Dc / 128, Hc), 256, SMY>>>(
            gVh + (size_t)l * Hc * Dc * Dc, gVl + (size_t)l * Hc * Dc * Dc,
            gXh, gXl, gY, nullptr, nullptr, nullptr,
            Dc, Nc, Dc, (long long)Dc * Dc, (long long)Dc * Nc,
            nullptr, nullptr, 4);

        // 3) fused gram+argmax+scatter: attn (already = X) += scatter
        gram_argmax_scatter<<<dim3(Nc / 64, Hc), 256, SMGR>>>(gKXh, gKXl, gY, gAttn);

        // 4) attn planes
        split_kernel<<<(Dc * Nc / 4 + 255) / 256, 256>>>(
            (const float4*)gAttn, gAth, gAtl, nullptr, Dc * Nc / 4);

        // 5) ff1 planes = relu(W1_l @ attn + b1)  (mode 9)
        bf16_gemm<128, 256, 2, 4, 4><<<dim3(Nc / 256, DFFc / 128, 1), 256, SMY>>>(
            gW1h + (size_t)l * DFFc * Dc, gW1l + (size_t)l * DFFc * Dc,
            gAth, gAtl, nullptr, nullptr, gF1h, gF1l,
            DFFc, Nc, Dc, 0, 0, b1l, nullptr, 9);

        // 6) X = attn + W2_l @ ff1 + b2
        //    last layer: write straight to d_out (mode 6), no planes/copy needed
        if (last) {
            bf16_gemm<64, 128, 2, 4, 4><<<dim3(Nc / 128, Dc / 64, 1), 256, SMF2>>>(
                gW2h + (size_t)l * Dc * DFFc, gW2l + (size_t)l * Dc * DFFc,
                gF1h, gF1l, (float*)d_out, nullptr, nullptr, nullptr,
                Dc, Nc, DFFc, 0, 0, b2l, gAttn, 6);
        } else {
            bf16_gemm<64, 128, 2, 4, 4><<<dim3(Nc / 128, Dc / 64, 1), 256, SMF2>>>(
                gW2h + (size_t)l * Dc * DFFc, gW2l + (size_t)l * Dc * DFFc,
                gF1h, gF1l, gX, gAttn, gXh, gXl,
                Dc, Nc, DFFc, 0, 0, b2l, gAttn, 46);
        }
    }
}

// round 11
// speedup vs baseline: 1.0372x; 1.0319x over previous
#include <cuda_runtime.h>
#include <cuda_bf16.h>
#include <mma.h>
#include <cstdint>

using namespace nvcuda;

#define Lc   8
#define Hc   4
#define Qc   64
#define Dc   512
#define Nc   2048
#define DFFc 2048
#define KVROWS (Hc * Dc + Hc * Qc)   // 2304: V rows then K rows
#define YROWS  (Hc * Dc)             // 2048

// ---------------- device scratch (no allocations allowed) ----------------
__device__ float g_X[Dc * Nc];
__device__ float g_attn[Dc * Nc];
__device__ float g_Y[Hc * Dc * Nc];
__device__ __nv_bfloat16 g_KVh[Lc * KVROWS * Dc], g_KVl[Lc * KVROWS * Dc];
__device__ __nv_bfloat16 g_W1h[Lc * DFFc * Dc],   g_W1l[Lc * DFFc * Dc];
__device__ __nv_bfloat16 g_W2h[Lc * Dc * DFFc],   g_W2l[Lc * Dc * DFFc];
__device__ __nv_bfloat16 g_Xh[Dc * Nc],           g_Xl[Dc * Nc];
__device__ __nv_bfloat16 g_Ath[Dc * Nc],          g_Atl[Dc * Nc];
__device__ __nv_bfloat16 g_F1h[DFFc * Nc],        g_F1l[DFFc * Nc];
__device__ __nv_bfloat16 g_KXh[Hc * Qc * Nc],     g_KXl[Hc * Qc * Nc];

// ---------------- helpers --------------------------------------------------
__device__ __forceinline__ uint32_t smem_u32(const void* p) {
    uint32_t a;
    asm("{ .reg .u64 t; cvta.to.shared.u64 t, %1; cvt.u32.u64 %0, t; }"
        : "=r"(a) : "l"(p));
    return a;
}
__device__ __forceinline__ void cp16(void* s, const void* g) {
    asm volatile("cp.async.cg.shared.global [%0], [%1], 16;"
                 :: "r"(smem_u32(s)), "l"(g) : "memory");
}
__device__ __forceinline__ void cp_commit() {
    asm volatile("cp.async.commit_group;" ::: "memory");
}
template<int N> __device__ __forceinline__ void cp_wait() {
    asm volatile("cp.async.wait_group %0;" :: "n"(N) : "memory");
}

__device__ __forceinline__ void split_store4(__nv_bfloat16* __restrict__ Hd,
                                             __nv_bfloat16* __restrict__ Ld,
                                             float4 v)
{
    __nv_bfloat162 h0 = __floats2bfloat162_rn(v.x, v.y);
    __nv_bfloat162 h1 = __floats2bfloat162_rn(v.z, v.w);
    float2 f0 = __bfloat1622float2(h0);
    float2 f1 = __bfloat1622float2(h1);
    __nv_bfloat162 l0 = __floats2bfloat162_rn(v.x - f0.x, v.y - f0.y);
    __nv_bfloat162 l1 = __floats2bfloat162_rn(v.z - f1.x, v.w - f1.y);
    *(__nv_bfloat162*)(Hd)     = h0;
    *(__nv_bfloat162*)(Hd + 2) = h1;
    *(__nv_bfloat162*)(Ld)     = l0;
    *(__nv_bfloat162*)(Ld + 2) = l1;
}

__device__ __forceinline__ unsigned enc_f(float f) {
    unsigned u = __float_as_uint(f);
    return (u & 0x80000000u) ? ~u : (u | 0x80000000u);
}
__device__ __forceinline__ float dec_f(unsigned v) {
    return __uint_as_float((v & 0x80000000u) ? (v ^ 0x80000000u) : ~v);
}

// ---------------- fp32 -> bf16 h/l plane split (+optional fp32 copy) ------
__global__ void __launch_bounds__(256) split_kernel(
    const float4* __restrict__ src,
    __nv_bfloat16* __restrict__ h, __nv_bfloat16* __restrict__ l,
    float4* __restrict__ copy, int n4)
{
    int i = blockIdx.x * 256 + threadIdx.x;
    if (i < n4) {
        float4 v = src[i];
        split_store4(h + (size_t)i * 4, l + (size_t)i * 4, v);
        if (copy) copy[i] = v;
    }
}

// ---------------- pack V_l (2048 rows) + K_l (256 rows) into KV planes ----
__global__ void __launch_bounds__(256) pack_kv(
    const float4* __restrict__ V, const float4* __restrict__ K,
    __nv_bfloat16* __restrict__ h, __nv_bfloat16* __restrict__ l)
{
    constexpr int PER_L = KVROWS * (Dc / 4);      // 294912 float4 per layer
    int i = blockIdx.x * 256 + threadIdx.x;
    if (i >= Lc * PER_L) return;
    const int lay = i / PER_L;
    const int rem = i % PER_L;
    const int row = rem >> 7;                      // Dc/4 = 128
    const int c4  = rem & 127;
    float4 v;
    if (row < YROWS)
        v = V[((size_t)lay * YROWS + row) * 128 + c4];
    else
        v = K[((size_t)lay * (Hc * Qc) + row - YROWS) * 128 + c4];
    split_store4(h + (size_t)i * 4, l + (size_t)i * 4, v);
}

// ============ bf16-plane 3x GEMM with cp.async multistage pipeline ========
// A:[M,K] (h/l planes), B:[K,N] (h/l planes), all row-major bf16.
// mode bits: 1=relu(+bias), 2=residual(+bias), 4=write fp32 C,
//            8=write h+l planes, 32=also write fp32 C2.
// mode==4 exactly -> direct wmma store.
// mode==64 -> combined KV: rows < YROWS direct-store to C (Y), rows >= YROWS
//            emit h/l planes at row-YROWS (KX).
template<int BM, int BN, int WM, int WN, int S>
__global__ void __launch_bounds__(WM * WN * 32) bf16_gemm(
    const __nv_bfloat16* __restrict__ Ah, const __nv_bfloat16* __restrict__ Al,
    const __nv_bfloat16* __restrict__ Bh, const __nv_bfloat16* __restrict__ Bl,
    float* __restrict__ C, float* __restrict__ C2,
    __nv_bfloat16* __restrict__ Ch, __nv_bfloat16* __restrict__ Cl,
    int M, int N, int K, long long strideA, long long strideC,
    const float* __restrict__ bias, const float* __restrict__ R, int mode)
{
    constexpr int TH = WM * WN * 32;
    constexpr int BK = 32;
    constexpr int AP = 40;
    constexpr int BP = BN + 8;
    constexpr int ABYT = BM * AP * 2;
    constexpr int BBYT = BK * BP * 2;
    constexpr int STG = 2 * ABYT + 2 * BBYT;
    constexpr int MF = BM / (WM * 16);
    constexpr int NF = BN / (WN * 16);
    constexpr int AIT = BM * (BK / 8) / TH;
    constexpr int BIT = BK * (BN / 8) / TH;

    extern __shared__ char sm[];
    const int tid = threadIdx.x, w = tid >> 5;
    Ah += (size_t)blockIdx.z * strideA;
    Al += (size_t)blockIdx.z * strideA;
    if (C) C += (size_t)blockIdx.z * strideC;
    const int bm = blockIdx.y * BM;
    const int bn = blockIdx.x * BN;
    const int wm0 = (w % WM) * (MF * 16);
    const int wn0 = (w / WM) * (NF * 16);
    const int KT = K / BK;

    auto issue = [&](int tile) {
        const int k0 = tile * BK;
        char* st = sm + (tile % S) * STG;
        __nv_bfloat16* sAh = (__nv_bfloat16*)st;
        __nv_bfloat16* sAl = (__nv_bfloat16*)(st + ABYT);
        __nv_bfloat16* sBh = (__nv_bfloat16*)(st + 2 * ABYT);
        __nv_bfloat16* sBl = (__nv_bfloat16*)(st + 2 * ABYT + BBYT);
#pragma unroll
        for (int p = 0; p < AIT; p++) {
            const int c = tid + p * TH;
            const int r = c >> 2, c8 = (c & 3) * 8;
            cp16(sAh + r * AP + c8, Ah + (size_t)(bm + r) * K + k0 + c8);
            cp16(sAl + r * AP + c8, Al + (size_t)(bm + r) * K + k0 + c8);
        }
#pragma unroll
        for (int p = 0; p < BIT; p++) {
            const int c = tid + p * TH;
            const int r = c / (BN / 8), c8 = (c % (BN / 8)) * 8;
            cp16(sBh + r * BP + c8, Bh + (size_t)(k0 + r) * N + bn + c8);
            cp16(sBl + r * BP + c8, Bl + (size_t)(k0 + r) * N + bn + c8);
        }
    };

    wmma::fragment<wmma::accumulator, 16, 16, 16, float> acc[MF][NF];
#pragma unroll
    for (int i = 0; i < MF; i++)
#pragma unroll
        for (int j = 0; j < NF; j++) wmma::fill_fragment(acc[i][j], 0.f);

#pragma unroll
    for (int t = 0; t < S - 1; t++) {
        if (t < KT) issue(t);
        cp_commit();
    }

#pragma unroll 1
    for (int kt = 0; kt < KT; kt++) {
        cp_wait<S - 2>();
        __syncthreads();
        if (kt + S - 1 < KT) issue(kt + S - 1);
        cp_commit();

        char* st = sm + (kt % S) * STG;
        const __nv_bfloat16* sAh = (const __nv_bfloat16*)st;
        const __nv_bfloat16* sAl = (const __nv_bfloat16*)(st + ABYT);
        const __nv_bfloat16* sBh = (const __nv_bfloat16*)(st + 2 * ABYT);
        const __nv_bfloat16* sBl = (const __nv_bfloat16*)(st + 2 * ABYT + BBYT);

#pragma unroll
        for (int kks = 0; kks < 2; kks++) {
            const int kk = kks * 16;
            wmma::fragment<wmma::matrix_a, 16, 16, 16, __nv_bfloat16, wmma::row_major> fAh[MF];
            wmma::fragment<wmma::matrix_b, 16, 16, 16, __nv_bfloat16, wmma::row_major> fBh[NF];
#pragma unroll
            for (int i = 0; i < MF; i++)
                wmma::load_matrix_sync(fAh[i], sAh + (wm0 + i * 16) * AP + kk, AP);
#pragma unroll
            for (int j = 0; j < NF; j++)
                wmma::load_matrix_sync(fBh[j], sBh + kk * BP + wn0 + j * 16, BP);
#pragma unroll
            for (int i = 0; i < MF; i++)
#pragma unroll
                for (int j = 0; j < NF; j++)
                    wmma::mma_sync(acc[i][j], fAh[i], fBh[j], acc[i][j]);
            {
                wmma::fragment<wmma::matrix_b, 16, 16, 16, __nv_bfloat16, wmma::row_major> fBl[NF];
#pragma unroll
                for (int j = 0; j < NF; j++)
                    wmma::load_matrix_sync(fBl[j], sBl + kk * BP + wn0 + j * 16, BP);
#pragma unroll
                for (int i = 0; i < MF; i++)
#pragma unroll
                    for (int j = 0; j < NF; j++)
                        wmma::mma_sync(acc[i][j], fAh[i], fBl[j], acc[i][j]);
            }
            {
                wmma::fragment<wmma::matrix_a, 16, 16, 16, __nv_bfloat16, wmma::row_major> fAl[MF];
#pragma unroll
                for (int i = 0; i < MF; i++)
                    wmma::load_matrix_sync(fAl[i], sAl + (wm0 + i * 16) * AP + kk, AP);
#pragma unroll
                for (int i = 0; i < MF; i++)
#pragma unroll
                    for (int j = 0; j < NF; j++)
                        wmma::mma_sync(acc[i][j], fAl[i], fBh[j], acc[i][j]);
            }
        }
    }

    if (mode == 4) {
#pragma unroll
        for (int i = 0; i < MF; i++)
#pragma unroll
            for (int j = 0; j < NF; j++)
                wmma::store_matrix_sync(
                    &C[(size_t)(bm + wm0 + i * 16) * N + bn + wn0 + j * 16],
                    acc[i][j], N, wmma::mem_row_major);
        return;
    }

    if (mode == 64) {
        if (bm < YROWS) {
            // Y region: direct fp32 store
#pragma unroll
            for (int i = 0; i < MF; i++)
#pragma unroll
                for (int j = 0; j < NF; j++)
                    wmma::store_matrix_sync(
                        &C[(size_t)(bm + wm0 + i * 16) * N + bn + wn0 + j * 16],
                        acc[i][j], N, wmma::mem_row_major);
        } else {
            // KX region: stage, then split to h/l planes at row - YROWS
            __syncthreads();
            float* cs = (float*)sm;
#pragma unroll
            for (int i = 0; i < MF; i++)
#pragma unroll
                for (int j = 0; j < NF; j++)
                    wmma::store_matrix_sync(
                        cs + (size_t)(wm0 + i * 16) * BN + wn0 + j * 16,
                        acc[i][j], BN, wmma::mem_row_major);
            __syncthreads();
            constexpr int CIT2 = BM * BN / 4 / TH;
#pragma unroll
            for (int p = 0; p < CIT2; p++) {
                const int id = tid + p * TH;
                const int row = id / (BN / 4), c4 = id % (BN / 4);
                float4 v = ((const float4*)cs)[id];
                const int gr = bm + row - YROWS;
                const int gc = bn + c4 * 4;
                split_store4(Ch + (size_t)gr * N + gc,
                             Cl + (size_t)gr * N + gc, v);
            }
        }
        return;
    }

    __syncthreads();
    float* cs = (float*)sm;
#pragma unroll
    for (int i = 0; i < MF; i++)
#pragma unroll
        for (int j = 0; j < NF; j++)
            wmma::store_matrix_sync(cs + (size_t)(wm0 + i * 16) * BN + wn0 + j * 16,
                                    acc[i][j], BN, wmma::mem_row_major);
    __syncthreads();

    constexpr int CIT = BM * BN / 4 / TH;
#pragma unroll
    for (int p = 0; p < CIT; p++) {
        const int id = tid + p * TH;
        const int row = id / (BN / 4), c4 = id % (BN / 4);
        float4 v = ((const float4*)cs)[id];
        const int gr = bm + row;
        const int gc = bn + c4 * 4;
        if (mode & 3) {
            const float bv = bias[gr];
            v.x += bv; v.y += bv; v.z += bv; v.w += bv;
        }
        if (mode & 1) {
            v.x = fmaxf(v.x, 0.f); v.y = fmaxf(v.y, 0.f);
            v.z = fmaxf(v.z, 0.f); v.w = fmaxf(v.w, 0.f);
        }
        if (mode & 2) {
            float4 r4 = *(const float4*)&R[(size_t)gr * N + gc];
            v.x += r4.x; v.y += r4.y; v.z += r4.z; v.w += r4.w;
        }
        if (mode & 4)  *(float4*)&C[(size_t)gr * N + gc] = v;
        if (mode & 32) *(float4*)&C2[(size_t)gr * N + gc] = v;
        if (mode & 8)  split_store4(Ch + (size_t)gr * N + gc,
                                    Cl + (size_t)gr * N + gc, v);
    }
}

// ====== fused gram + argmax + scatter (bf16 planes, 3-product) =============
#define CAND 96
__global__ void __launch_bounds__(256) gram_argmax_scatter(
    const __nv_bfloat16* __restrict__ KXh, const __nv_bfloat16* __restrict__ KXl,
    const float* __restrict__ Y, float* __restrict__ attn)
{
    constexpr int AP = 72, BP = 136, CP = 132;
    extern __shared__ char sm[];
    __nv_bfloat16* aH = (__nv_bfloat16*)sm;                 // 9216
    __nv_bfloat16* aL = (__nv_bfloat16*)(sm + 9216);        // 9216
    float*    Cs   = (float*)(sm + 88064);                  // 33792
    unsigned* rm   = (unsigned*)(sm + 121856);
    int*      cnt  = (int*)(sm + 122112);
    float*    wrow = (float*)(sm + 122368);
    int*      cm   = (int*)(sm + 122624);                   // 24576
    float*    csv  = (float*)(sm + 147200);                 // 24576 -> 171776

    const int h  = blockIdx.y;
    const int r0 = blockIdx.x * 64;
    const __nv_bfloat16* Ahg = KXh + (size_t)h * Qc * Nc;
    const __nv_bfloat16* Alg = KXl + (size_t)h * Qc * Nc;
    const int tid = threadIdx.x, w = tid >> 5, lane = tid & 31;
    const int wm0 = (w & 1) * 32, wn0 = (w >> 1) * 32;

    if (tid < 64) { rm[tid] = enc_f(-1e30f); cnt[tid] = 0; }

    auto issueB = [&](int mt, int s) {
        const int m0 = mt * 128;
        __nv_bfloat16* bH = (__nv_bfloat16*)(sm + 18432 + s * 34816);
        __nv_bfloat16* bL = (__nv_bfloat16*)(sm + 18432 + s * 34816 + 17408);
#pragma unroll
        for (int p = 0; p < 4; p++) {
            const int c = tid + p * 256;
            const int q = c >> 4, c8 = (c & 15) * 8;
            cp16(bH + q * BP + c8, Ahg + (size_t)q * Nc + m0 + c8);
            cp16(bL + q * BP + c8, Alg + (size_t)q * Nc + m0 + c8);
        }
    };

#pragma unroll
    for (int p = 0; p < 2; p++) {
        const int c = tid + p * 256;
        const int q = c >> 3, c8 = (c & 7) * 8;
        cp16(aH + q * AP + c8, Ahg + (size_t)q * Nc + r0 + c8);
        cp16(aL + q * AP + c8, Alg + (size_t)q * Nc + r0 + c8);
    }
    issueB(0, 0);
    cp_commit();

    for (int mt = 0; mt < Nc / 128; mt++) {
        if (mt + 1 < Nc / 128) issueB(mt + 1, (mt + 1) & 1);
        cp_commit();
        cp_wait<1>();
        __syncthreads();

        const __nv_bfloat16* bH = (const __nv_bfloat16*)(sm + 18432 + (mt & 1) * 34816);
        const __nv_bfloat16* bL = (const __nv_bfloat16*)(sm + 18432 + (mt & 1) * 34816 + 17408);

        wmma::fragment<wmma::accumulator, 16, 16, 16, float> acc[2][2];
#pragma unroll
        for (int i = 0; i < 2; i++)
#pragma unroll
            for (int j = 0; j < 2; j++) wmma::fill_fragment(acc[i][j], 0.f);

#pragma unroll
        for (int kks = 0; kks < 4; kks++) {
            const int kk = kks * 16;
            wmma::fragment<wmma::matrix_a, 16, 16, 16, __nv_bfloat16, wmma::col_major> fAh[2];
            wmma::fragment<wmma::matrix_b, 16, 16, 16, __nv_bfloat16, wmma::row_major> fBh[2];
#pragma unroll
            for (int i = 0; i < 2; i++)
                wmma::load_matrix_sync(fAh[i], aH + kk * AP + wm0 + i * 16, AP);
#pragma unroll
            for (int j = 0; j < 2; j++)
                wmma::load_matrix_sync(fBh[j], bH + kk * BP + wn0 + j * 16, BP);
#pragma unroll
            for (int i = 0; i < 2; i++)
#pragma unroll
                for (int j = 0; j < 2; j++)
                    wmma::mma_sync(acc[i][j], fAh[i], fBh[j], acc[i][j]);
            {
                wmma::fragment<wmma::matrix_b, 16, 16, 16, __nv_bfloat16, wmma::row_major> fBl[2];
#pragma unroll
                for (int j = 0; j < 2; j++)
                    wmma::load_matrix_sync(fBl[j], bL + kk * BP + wn0 + j * 16, BP);
#pragma unroll
                for (int i = 0; i < 2; i++)
#pragma unroll
                    for (int j = 0; j < 2; j++)
                        wmma::mma_sync(acc[i][j], fAh[i], fBl[j], acc[i][j]);
            }
            {
                wmma::fragment<wmma::matrix_a, 16, 16, 16, __nv_bfloat16, wmma::col_major> fAl[2];
#pragma unroll
                for (int i = 0; i < 2; i++)
                    wmma::load_matrix_sync(fAl[i], aL + kk * AP + wm0 + i * 16, AP);
#pragma unroll
                for (int i = 0; i < 2; i++)
#pragma unroll
                    for (int j = 0; j < 2; j++)
                        wmma::mma_sync(acc[i][j], fAl[i], fBh[j], acc[i][j]);
            }
        }
#pragma unroll
        for (int i = 0; i < 2; i++)
#pragma unroll
            for (int j = 0; j < 2; j++)
                wmma::store_matrix_sync(Cs + (wm0 + i * 16) * CP + wn0 + j * 16,
                                        acc[i][j], CP, wmma::mem_row_major);
        __syncthreads();

        const int r = tid >> 2;
        const int c0 = (tid & 3) * 32;
        float tm = -1e30f;
#pragma unroll
        for (int c = 0; c < 32; c++) tm = fmaxf(tm, Cs[r * CP + c0 + c]);
        tm = fmaxf(tm, __shfl_xor_sync(0xffffffffu, tm, 1, 4));
        tm = fmaxf(tm, __shfl_xor_sync(0xffffffffu, tm, 2, 4));
        if ((tid & 3) == 0) atomicMax(&rm[r], enc_f(tm));
        __syncthreads();

        const float thr = dec_f(rm[r]) - 0.5f;
        const int m0 = mt * 128;
#pragma unroll
        for (int c = 0; c < 32; c++) {
            const float v = Cs[r * CP + c0 + c];
            if (v >= thr) {
                int pos = atomicAdd(&cnt[r], 1);
                if (pos < CAND) {
                    cm[r * CAND + pos]  = m0 + c0 + c;
                    csv[r * CAND + pos] = v;
                }
            }
        }
        __syncthreads();
    }

    if (tid < 64) {
        const float fmax = dec_f(rm[tid]);
        const float thrF = fmax - 0.5f;
        const int nc = cnt[tid] < CAND ? cnt[tid] : CAND;
        int hits = 0;
        for (int j = 0; j < nc; j++) {
            if (csv[tid * CAND + j] >= thrF) {
                cm[tid * CAND + hits] = cm[tid * CAND + j];
                hits++;
            }
        }
        cnt[tid] = hits;
        wrow[tid] = (fabsf(fmax) > 0.5f && hits > 0) ? 1.f / (float)hits : 0.f;
    }
    __syncthreads();

    const float* Yh = Y + (size_t)h * Dc * Nc;
    for (int rr = 0; rr < 8; rr++) {
        const int r = w * 8 + rr;
        const float wv = wrow[r];
        const int hits = cnt[r];
        if (wv == 0.f || hits == 0) continue;
        const int n = r0 + r;
        float yv[16];
#pragma unroll
        for (int p = 0; p < 16; p++)
            yv[p] = wv * Yh[(size_t)(lane + p * 32) * Nc + n];
        for (int j = 0; j < hits; j++) {
            const int m = cm[r * CAND + j];
#pragma unroll
            for (int p = 0; p < 16; p++)
                atomicAdd(&attn[(size_t)(lane + p * 32) * Nc + m], yv[p]);
        }
    }
}

// --------------------------------------------------------------------------
extern "C" void kernel_launch(void* const* d_in, const int* in_sizes, int n_in,
                              void* d_out, int out_size)
{
    const float* X  = (const float*)d_in[0];
    const float* Kp = (const float*)d_in[1];
    const float* Vp = (const float*)d_in[2];
    const float* W1 = (const float*)d_in[3];
    const float* b1 = (const float*)d_in[4];
    const float* W2 = (const float*)d_in[5];
    const float* b2 = (const float*)d_in[6];

    float *gX, *gAttn, *gY;
    __nv_bfloat16 *gKVh, *gKVl, *gW1h, *gW1l, *gW2h, *gW2l;
    __nv_bfloat16 *gXh, *gXl, *gAth, *gAtl, *gF1h, *gF1l, *gKXh, *gKXl;
    cudaGetSymbolAddress((void**)&gX,   g_X);
    cudaGetSymbolAddress((void**)&gAttn,g_attn);
    cudaGetSymbolAddress((void**)&gY,   g_Y);
    cudaGetSymbolAddress((void**)&gKVh, g_KVh);  cudaGetSymbolAddress((void**)&gKVl, g_KVl);
    cudaGetSymbolAddress((void**)&gW1h, g_W1h);  cudaGetSymbolAddress((void**)&gW1l, g_W1l);
    cudaGetSymbolAddress((void**)&gW2h, g_W2h);  cudaGetSymbolAddress((void**)&gW2l, g_W2l);
    cudaGetSymbolAddress((void**)&gXh,  g_Xh);   cudaGetSymbolAddress((void**)&gXl,  g_Xl);
    cudaGetSymbolAddress((void**)&gAth, g_Ath);  cudaGetSymbolAddress((void**)&gAtl, g_Atl);
    cudaGetSymbolAddress((void**)&gF1h, g_F1h);  cudaGetSymbolAddress((void**)&gF1l, g_F1l);
    cudaGetSymbolAddress((void**)&gKXh, g_KXh);  cudaGetSymbolAddress((void**)&gKXl, g_KXl);

    const int SMY  = 4 * (2 * 128 * 40 * 2 + 2 * 32 * 264 * 2);   // 217088
    const int SMF2 = 4 * (2 *  64 * 40 * 2 + 2 * 32 * 136 * 2);   // 110592
    const int SMGR = 171776;
    cudaFuncSetAttribute(bf16_gemm<128, 256, 2, 4, 4>,
                         cudaFuncAttributeMaxDynamicSharedMemorySize, SMY);
    cudaFuncSetAttribute(bf16_gemm<64, 128, 2, 4, 4>,
                         cudaFuncAttributeMaxDynamicSharedMemorySize, SMF2);
    cudaFuncSetAttribute(gram_argmax_scatter,
                         cudaFuncAttributeMaxDynamicSharedMemorySize, SMGR);

    {
        const int nW  = Lc * DFFc * Dc / 4;
        const int nX  = Dc * Nc / 4;
        const int nKV = Lc * KVROWS * Dc / 4;
        pack_kv<<<(nKV + 255) / 256, 256>>>((const float4*)Vp, (const float4*)Kp,
                                            gKVh, gKVl);
        split_kernel<<<(nW + 255) / 256, 256>>>((const float4*)W1, gW1h, gW1l, nullptr, nW);
        split_kernel<<<(nW + 255) / 256, 256>>>((const float4*)W2, gW2h, gW2l, nullptr, nW);
        // X split also seeds attn = X for layer 0
        split_kernel<<<(nX + 255) / 256, 256>>>((const float4*)X, gXh, gXl,
                                                (float4*)gAttn, nX);
    }

    for (int l = 0; l < Lc; l++) {
        const float* b1l = b1 + (size_t)l * DFFc;
        const float* b2l = b2 + (size_t)l * Dc;
        const bool last = (l == Lc - 1);

        // 1) [Y; KX] = [V_l; K_l] @ X  (merged, mode 64, 144 blocks = 1 wave)
        bf16_gemm<128, 256, 2, 4, 4><<<dim3(Nc / 256, KVROWS / 128, 1), 256, SMY>>>(
            gKVh + (size_t)l * KVROWS * Dc, gKVl + (size_t)l * KVROWS * Dc,
            gXh, gXl, gY, nullptr, gKXh, gKXl,
            KVROWS, Nc, Dc, 0, 0, nullptr, nullptr, 64);

        // 2) fused gram+argmax+scatter: attn (already = X) += scatter
        gram_argmax_scatter<<<dim3(Nc / 64, Hc), 256, SMGR>>>(gKXh, gKXl, gY, gAttn);

        // 3) attn planes
        split_kernel<<<(Dc * Nc / 4 + 255) / 256, 256>>>(
            (const float4*)gAttn, gAth, gAtl, nullptr, Dc * Nc / 4);

        // 4) ff1 planes = relu(W1_l @ attn + b1)  (mode 9)
        bf16_gemm<128, 256, 2, 4, 4><<<dim3(Nc / 256, DFFc / 128, 1), 256, SMY>>>(
            gW1h + (size_t)l * DFFc * Dc, gW1l + (size_t)l * DFFc * Dc,
            gAth, gAtl, nullptr, nullptr, gF1h, gF1l,
            DFFc, Nc, Dc, 0, 0, b1l, nullptr, 9);

        // 5) X = attn + W2_l @ ff1 + b2
        if (last) {
            bf16_gemm<64, 128, 2, 4, 4><<<dim3(Nc / 128, Dc / 64, 1), 256, SMF2>>>(
                gW2h + (size_t)l * Dc * DFFc, gW2l + (size_t)l * Dc * DFFc,
                gF1h, gF1l, (float*)d_out, nullptr, nullptr, nullptr,
                Dc, Nc, DFFc, 0, 0, b2l, gAttn, 6);
        } else {
            bf16_gemm<64, 128, 2, 4, 4><<<dim3(Nc / 128, Dc / 64, 1), 256, SMF2>>>(
                gW2h + (size_t)l * Dc * DFFc, gW2l + (size_t)l * Dc * DFFc,
                gF1h, gF1l, gX, gAttn, gXh, gXl,
                Dc, Nc, DFFc, 0, 0, b2l, gAttn, 46);
        }
    }
}

// round 12
// speedup vs baseline: 1.0978x; 1.0585x over previous
#include <cuda_runtime.h>
#include <cuda_bf16.h>
#include <mma.h>
#include <cstdint>

using namespace nvcuda;

#define Lc   8
#define Hc   4
#define Qc   64
#define Dc   512
#define Nc   2048
#define DFFc 2048
#define KVROWS (Hc * Dc + Hc * Qc)   // 2304: V rows then K rows
#define YROWS  (Hc * Dc)             // 2048

// ---------------- device scratch (no allocations allowed) ----------------
__device__ float g_X[Dc * Nc];
__device__ float g_attn[Dc * Nc];
__device__ float g_Y[Hc * Nc * Dc];   // TRANSPOSED: Yt[h][n][d], d contiguous
__device__ __nv_bfloat16 g_KVh[Lc * KVROWS * Dc], g_KVl[Lc * KVROWS * Dc];
__device__ __nv_bfloat16 g_W1h[Lc * DFFc * Dc],   g_W1l[Lc * DFFc * Dc];
__device__ __nv_bfloat16 g_W2h[Lc * Dc * DFFc],   g_W2l[Lc * Dc * DFFc];
__device__ __nv_bfloat16 g_Xh[Dc * Nc],           g_Xl[Dc * Nc];
__device__ __nv_bfloat16 g_Ath[Dc * Nc],          g_Atl[Dc * Nc];
__device__ __nv_bfloat16 g_F1h[DFFc * Nc],        g_F1l[DFFc * Nc];
__device__ __nv_bfloat16 g_KXh[Hc * Qc * Nc],     g_KXl[Hc * Qc * Nc];

// ---------------- helpers --------------------------------------------------
__device__ __forceinline__ uint32_t smem_u32(const void* p) {
    uint32_t a;
    asm("{ .reg .u64 t; cvta.to.shared.u64 t, %1; cvt.u32.u64 %0, t; }"
        : "=r"(a) : "l"(p));
    return a;
}
__device__ __forceinline__ void cp16(void* s, const void* g) {
    asm volatile("cp.async.cg.shared.global [%0], [%1], 16;"
                 :: "r"(smem_u32(s)), "l"(g) : "memory");
}
__device__ __forceinline__ void cp_commit() {
    asm volatile("cp.async.commit_group;" ::: "memory");
}
template<int N> __device__ __forceinline__ void cp_wait() {
    asm volatile("cp.async.wait_group %0;" :: "n"(N) : "memory");
}

__device__ __forceinline__ void split_store4(__nv_bfloat16* __restrict__ Hd,
                                             __nv_bfloat16* __restrict__ Ld,
                                             float4 v)
{
    __nv_bfloat162 h0 = __floats2bfloat162_rn(v.x, v.y);
    __nv_bfloat162 h1 = __floats2bfloat162_rn(v.z, v.w);
    float2 f0 = __bfloat1622float2(h0);
    float2 f1 = __bfloat1622float2(h1);
    __nv_bfloat162 l0 = __floats2bfloat162_rn(v.x - f0.x, v.y - f0.y);
    __nv_bfloat162 l1 = __floats2bfloat162_rn(v.z - f1.x, v.w - f1.y);
    *(__nv_bfloat162*)(Hd)     = h0;
    *(__nv_bfloat162*)(Hd + 2) = h1;
    *(__nv_bfloat162*)(Ld)     = l0;
    *(__nv_bfloat162*)(Ld + 2) = l1;
}

__device__ __forceinline__ unsigned enc_f(float f) {
    unsigned u = __float_as_uint(f);
    return (u & 0x80000000u) ? ~u : (u | 0x80000000u);
}
__device__ __forceinline__ float dec_f(unsigned v) {
    return __uint_as_float((v & 0x80000000u) ? (v ^ 0x80000000u) : ~v);
}

// ---------------- fp32 -> bf16 h/l plane split (+optional fp32 copy) ------
__global__ void __launch_bounds__(256) split_kernel(
    const float4* __restrict__ src,
    __nv_bfloat16* __restrict__ h, __nv_bfloat16* __restrict__ l,
    float4* __restrict__ copy, int n4)
{
    int i = blockIdx.x * 256 + threadIdx.x;
    if (i < n4) {
        float4 v = src[i];
        split_store4(h + (size_t)i * 4, l + (size_t)i * 4, v);
        if (copy) copy[i] = v;
    }
}

// ---------------- pack V_l (2048 rows) + K_l (256 rows) into KV planes ----
__global__ void __launch_bounds__(256) pack_kv(
    const float4* __restrict__ V, const float4* __restrict__ K,
    __nv_bfloat16* __restrict__ h, __nv_bfloat16* __restrict__ l)
{
    constexpr int PER_L = KVROWS * (Dc / 4);
    int i = blockIdx.x * 256 + threadIdx.x;
    if (i >= Lc * PER_L) return;
    const int lay = i / PER_L;
    const int rem = i % PER_L;
    const int row = rem >> 7;
    const int c4  = rem & 127;
    float4 v;
    if (row < YROWS)
        v = V[((size_t)lay * YROWS + row) * 128 + c4];
    else
        v = K[((size_t)lay * (Hc * Qc) + row - YROWS) * 128 + c4];
    split_store4(h + (size_t)i * 4, l + (size_t)i * 4, v);
}

// ============ bf16-plane 3x GEMM with cp.async multistage pipeline ========
// A:[M,K] (h/l planes), B:[K,N] (h/l planes), all row-major bf16.
// mode bits: 1=relu(+bias), 2=residual(+bias), 4=write fp32 C,
//            8=write h+l planes, 32=also write fp32 C2.
// mode==4 exactly -> direct wmma store.
// mode==64 -> combined KV: rows < YROWS store Y TRANSPOSED into C as
//            Yt[h][n][d] (col-major tile store); rows >= YROWS emit h/l
//            planes at row-YROWS (KX).
template<int BM, int BN, int WM, int WN, int S>
__global__ void __launch_bounds__(WM * WN * 32) bf16_gemm(
    const __nv_bfloat16* __restrict__ Ah, const __nv_bfloat16* __restrict__ Al,
    const __nv_bfloat16* __restrict__ Bh, const __nv_bfloat16* __restrict__ Bl,
    float* __restrict__ C, float* __restrict__ C2,
    __nv_bfloat16* __restrict__ Ch, __nv_bfloat16* __restrict__ Cl,
    int M, int N, int K, long long strideA, long long strideC,
    const float* __restrict__ bias, const float* __restrict__ R, int mode)
{
    constexpr int TH = WM * WN * 32;
    constexpr int BK = 32;
    constexpr int AP = 40;
    constexpr int BP = BN + 8;
    constexpr int ABYT = BM * AP * 2;
    constexpr int BBYT = BK * BP * 2;
    constexpr int STG = 2 * ABYT + 2 * BBYT;
    constexpr int MF = BM / (WM * 16);
    constexpr int NF = BN / (WN * 16);
    constexpr int AIT = BM * (BK / 8) / TH;
    constexpr int BIT = BK * (BN / 8) / TH;

    extern __shared__ char sm[];
    const int tid = threadIdx.x, w = tid >> 5;
    Ah += (size_t)blockIdx.z * strideA;
    Al += (size_t)blockIdx.z * strideA;
    if (C) C += (size_t)blockIdx.z * strideC;
    const int bm = blockIdx.y * BM;
    const int bn = blockIdx.x * BN;
    const int wm0 = (w % WM) * (MF * 16);
    const int wn0 = (w / WM) * (NF * 16);
    const int KT = K / BK;

    auto issue = [&](int tile) {
        const int k0 = tile * BK;
        char* st = sm + (tile % S) * STG;
        __nv_bfloat16* sAh = (__nv_bfloat16*)st;
        __nv_bfloat16* sAl = (__nv_bfloat16*)(st + ABYT);
        __nv_bfloat16* sBh = (__nv_bfloat16*)(st + 2 * ABYT);
        __nv_bfloat16* sBl = (__nv_bfloat16*)(st + 2 * ABYT + BBYT);
#pragma unroll
        for (int p = 0; p < AIT; p++) {
            const int c = tid + p * TH;
            const int r = c >> 2, c8 = (c & 3) * 8;
            cp16(sAh + r * AP + c8, Ah + (size_t)(bm + r) * K + k0 + c8);
            cp16(sAl + r * AP + c8, Al + (size_t)(bm + r) * K + k0 + c8);
        }
#pragma unroll
        for (int p = 0; p < BIT; p++) {
            const int c = tid + p * TH;
            const int r = c / (BN / 8), c8 = (c % (BN / 8)) * 8;
            cp16(sBh + r * BP + c8, Bh + (size_t)(k0 + r) * N + bn + c8);
            cp16(sBl + r * BP + c8, Bl + (size_t)(k0 + r) * N + bn + c8);
        }
    };

    wmma::fragment<wmma::accumulator, 16, 16, 16, float> acc[MF][NF];
#pragma unroll
    for (int i = 0; i < MF; i++)
#pragma unroll
        for (int j = 0; j < NF; j++) wmma::fill_fragment(acc[i][j], 0.f);

#pragma unroll
    for (int t = 0; t < S - 1; t++) {
        if (t < KT) issue(t);
        cp_commit();
    }

#pragma unroll 1
    for (int kt = 0; kt < KT; kt++) {
        cp_wait<S - 2>();
        __syncthreads();
        if (kt + S - 1 < KT) issue(kt + S - 1);
        cp_commit();

        char* st = sm + (kt % S) * STG;
        const __nv_bfloat16* sAh = (const __nv_bfloat16*)st;
        const __nv_bfloat16* sAl = (const __nv_bfloat16*)(st + ABYT);
        const __nv_bfloat16* sBh = (const __nv_bfloat16*)(st + 2 * ABYT);
        const __nv_bfloat16* sBl = (const __nv_bfloat16*)(st + 2 * ABYT + BBYT);

#pragma unroll
        for (int kks = 0; kks < 2; kks++) {
            const int kk = kks * 16;
            wmma::fragment<wmma::matrix_a, 16, 16, 16, __nv_bfloat16, wmma::row_major> fAh[MF];
            wmma::fragment<wmma::matrix_b, 16, 16, 16, __nv_bfloat16, wmma::row_major> fBh[NF];
#pragma unroll
            for (int i = 0; i < MF; i++)
                wmma::load_matrix_sync(fAh[i], sAh + (wm0 + i * 16) * AP + kk, AP);
#pragma unroll
            for (int j = 0; j < NF; j++)
                wmma::load_matrix_sync(fBh[j], sBh + kk * BP + wn0 + j * 16, BP);
#pragma unroll
            for (int i = 0; i < MF; i++)
#pragma unroll
                for (int j = 0; j < NF; j++)
                    wmma::mma_sync(acc[i][j], fAh[i], fBh[j], acc[i][j]);
            {
                wmma::fragment<wmma::matrix_b, 16, 16, 16, __nv_bfloat16, wmma::row_major> fBl[NF];
#pragma unroll
                for (int j = 0; j < NF; j++)
                    wmma::load_matrix_sync(fBl[j], sBl + kk * BP + wn0 + j * 16, BP);
#pragma unroll
                for (int i = 0; i < MF; i++)
#pragma unroll
                    for (int j = 0; j < NF; j++)
                        wmma::mma_sync(acc[i][j], fAh[i], fBl[j], acc[i][j]);
            }
            {
                wmma::fragment<wmma::matrix_a, 16, 16, 16, __nv_bfloat16, wmma::row_major> fAl[MF];
#pragma unroll
                for (int i = 0; i < MF; i++)
                    wmma::load_matrix_sync(fAl[i], sAl + (wm0 + i * 16) * AP + kk, AP);
#pragma unroll
                for (int i = 0; i < MF; i++)
#pragma unroll
                    for (int j = 0; j < NF; j++)
                        wmma::mma_sync(acc[i][j], fAl[i], fBh[j], acc[i][j]);
            }
        }
    }

    if (mode == 4) {
#pragma unroll
        for (int i = 0; i < MF; i++)
#pragma unroll
            for (int j = 0; j < NF; j++)
                wmma::store_matrix_sync(
                    &C[(size_t)(bm + wm0 + i * 16) * N + bn + wn0 + j * 16],
                    acc[i][j], N, wmma::mem_row_major);
        return;
    }

    if (mode == 64) {
        if (bm < YROWS) {
            // Y region: transposed store -> Yt[h][n][d], d contiguous.
            // element (r = h*Dc + d, n) goes to C[h*Nc*Dc + n*Dc + d]
            const int h = bm / Dc;          // 128 | Dc, so whole block same head
            float* Yt = C + (size_t)h * Nc * Dc;
#pragma unroll
            for (int i = 0; i < MF; i++) {
                const int d0 = bm + wm0 + i * 16 - h * Dc;
#pragma unroll
                for (int j = 0; j < NF; j++)
                    wmma::store_matrix_sync(
                        Yt + (size_t)(bn + wn0 + j * 16) * Dc + d0,
                        acc[i][j], Dc, wmma::mem_col_major);
            }
        } else {
            // KX region: stage, then split to h/l planes at row - YROWS
            __syncthreads();
            float* cs = (float*)sm;
#pragma unroll
            for (int i = 0; i < MF; i++)
#pragma unroll
                for (int j = 0; j < NF; j++)
                    wmma::store_matrix_sync(
                        cs + (size_t)(wm0 + i * 16) * BN + wn0 + j * 16,
                        acc[i][j], BN, wmma::mem_row_major);
            __syncthreads();
            constexpr int CIT2 = BM * BN / 4 / TH;
#pragma unroll
            for (int p = 0; p < CIT2; p++) {
                const int id = tid + p * TH;
                const int row = id / (BN / 4), c4 = id % (BN / 4);
                float4 v = ((const float4*)cs)[id];
                const int gr = bm + row - YROWS;
                const int gc = bn + c4 * 4;
                split_store4(Ch + (size_t)gr * N + gc,
                             Cl + (size_t)gr * N + gc, v);
            }
        }
        return;
    }

    __syncthreads();
    float* cs = (float*)sm;
#pragma unroll
    for (int i = 0; i < MF; i++)
#pragma unroll
        for (int j = 0; j < NF; j++)
            wmma::store_matrix_sync(cs + (size_t)(wm0 + i * 16) * BN + wn0 + j * 16,
                                    acc[i][j], BN, wmma::mem_row_major);
    __syncthreads();

    constexpr int CIT = BM * BN / 4 / TH;
#pragma unroll
    for (int p = 0; p < CIT; p++) {
        const int id = tid + p * TH;
        const int row = id / (BN / 4), c4 = id % (BN / 4);
        float4 v = ((const float4*)cs)[id];
        const int gr = bm + row;
        const int gc = bn + c4 * 4;
        if (mode & 3) {
            const float bv = bias[gr];
            v.x += bv; v.y += bv; v.z += bv; v.w += bv;
        }
        if (mode & 1) {
            v.x = fmaxf(v.x, 0.f); v.y = fmaxf(v.y, 0.f);
            v.z = fmaxf(v.z, 0.f); v.w = fmaxf(v.w, 0.f);
        }
        if (mode & 2) {
            float4 r4 = *(const float4*)&R[(size_t)gr * N + gc];
            v.x += r4.x; v.y += r4.y; v.z += r4.z; v.w += r4.w;
        }
        if (mode & 4)  *(float4*)&C[(size_t)gr * N + gc] = v;
        if (mode & 32) *(float4*)&C2[(size_t)gr * N + gc] = v;
        if (mode & 8)  split_store4(Ch + (size_t)gr * N + gc,
                                    Cl + (size_t)gr * N + gc, v);
    }
}

// ====== fused gram + argmax + scatter (bf16 planes, 3-product) =============
// Y is TRANSPOSED: Yt[h][n][d], so per-row preloads are fully coalesced.
#define CAND 96
__global__ void __launch_bounds__(256) gram_argmax_scatter(
    const __nv_bfloat16* __restrict__ KXh, const __nv_bfloat16* __restrict__ KXl,
    const float* __restrict__ Yt, float* __restrict__ attn)
{
    constexpr int AP = 72, BP = 136, CP = 132;
    extern __shared__ char sm[];
    __nv_bfloat16* aH = (__nv_bfloat16*)sm;                 // 9216
    __nv_bfloat16* aL = (__nv_bfloat16*)(sm + 9216);        // 9216
    float*    Cs   = (float*)(sm + 88064);                  // 33792
    unsigned* rm   = (unsigned*)(sm + 121856);
    int*      cnt  = (int*)(sm + 122112);
    float*    wrow = (float*)(sm + 122368);
    int*      cm   = (int*)(sm + 122624);                   // 24576
    float*    csv  = (float*)(sm + 147200);                 // 24576 -> 171776

    const int h  = blockIdx.y;
    const int r0 = blockIdx.x * 64;
    const __nv_bfloat16* Ahg = KXh + (size_t)h * Qc * Nc;
    const __nv_bfloat16* Alg = KXl + (size_t)h * Qc * Nc;
    const int tid = threadIdx.x, w = tid >> 5, lane = tid & 31;
    const int wm0 = (w & 1) * 32, wn0 = (w >> 1) * 32;

    if (tid < 64) { rm[tid] = enc_f(-1e30f); cnt[tid] = 0; }

    auto issueB = [&](int mt, int s) {
        const int m0 = mt * 128;
        __nv_bfloat16* bH = (__nv_bfloat16*)(sm + 18432 + s * 34816);
        __nv_bfloat16* bL = (__nv_bfloat16*)(sm + 18432 + s * 34816 + 17408);
#pragma unroll
        for (int p = 0; p < 4; p++) {
            const int c = tid + p * 256;
            const int q = c >> 4, c8 = (c & 15) * 8;
            cp16(bH + q * BP + c8, Ahg + (size_t)q * Nc + m0 + c8);
            cp16(bL + q * BP + c8, Alg + (size_t)q * Nc + m0 + c8);
        }
    };

#pragma unroll
    for (int p = 0; p < 2; p++) {
        const int c = tid + p * 256;
        const int q = c >> 3, c8 = (c & 7) * 8;
        cp16(aH + q * AP + c8, Ahg + (size_t)q * Nc + r0 + c8);
        cp16(aL + q * AP + c8, Alg + (size_t)q * Nc + r0 + c8);
    }
    issueB(0, 0);
    cp_commit();

    for (int mt = 0; mt < Nc / 128; mt++) {
        if (mt + 1 < Nc / 128) issueB(mt + 1, (mt + 1) & 1);
        cp_commit();
        cp_wait<1>();
        __syncthreads();

        const __nv_bfloat16* bH = (const __nv_bfloat16*)(sm + 18432 + (mt & 1) * 34816);
        const __nv_bfloat16* bL = (const __nv_bfloat16*)(sm + 18432 + (mt & 1) * 34816 + 17408);

        wmma::fragment<wmma::accumulator, 16, 16, 16, float> acc[2][2];
#pragma unroll
        for (int i = 0; i < 2; i++)
#pragma unroll
            for (int j = 0; j < 2; j++) wmma::fill_fragment(acc[i][j], 0.f);

#pragma unroll
        for (int kks = 0; kks < 4; kks++) {
            const int kk = kks * 16;
            wmma::fragment<wmma::matrix_a, 16, 16, 16, __nv_bfloat16, wmma::col_major> fAh[2];
            wmma::fragment<wmma::matrix_b, 16, 16, 16, __nv_bfloat16, wmma::row_major> fBh[2];
#pragma unroll
            for (int i = 0; i < 2; i++)
                wmma::load_matrix_sync(fAh[i], aH + kk * AP + wm0 + i * 16, AP);
#pragma unroll
            for (int j = 0; j < 2; j++)
                wmma::load_matrix_sync(fBh[j], bH + kk * BP + wn0 + j * 16, BP);
#pragma unroll
            for (int i = 0; i < 2; i++)
#pragma unroll
                for (int j = 0; j < 2; j++)
                    wmma::mma_sync(acc[i][j], fAh[i], fBh[j], acc[i][j]);
            {
                wmma::fragment<wmma::matrix_b, 16, 16, 16, __nv_bfloat16, wmma::row_major> fBl[2];
#pragma unroll
                for (int j = 0; j < 2; j++)
                    wmma::load_matrix_sync(fBl[j], bL + kk * BP + wn0 + j * 16, BP);
#pragma unroll
                for (int i = 0; i < 2; i++)
#pragma unroll
                    for (int j = 0; j < 2; j++)
                        wmma::mma_sync(acc[i][j], fAh[i], fBl[j], acc[i][j]);
            }
            {
                wmma::fragment<wmma::matrix_a, 16, 16, 16, __nv_bfloat16, wmma::col_major> fAl[2];
#pragma unroll
                for (int i = 0; i < 2; i++)
                    wmma::load_matrix_sync(fAl[i], aL + kk * AP + wm0 + i * 16, AP);
#pragma unroll
                for (int i = 0; i < 2; i++)
#pragma unroll
                    for (int j = 0; j < 2; j++)
                        wmma::mma_sync(acc[i][j], fAl[i], fBh[j], acc[i][j]);
            }
        }
#pragma unroll
        for (int i = 0; i < 2; i++)
#pragma unroll
            for (int j = 0; j < 2; j++)
                wmma::store_matrix_sync(Cs + (wm0 + i * 16) * CP + wn0 + j * 16,
                                        acc[i][j], CP, wmma::mem_row_major);
        __syncthreads();

        const int r = tid >> 2;
        const int c0 = (tid & 3) * 32;
        float tm = -1e30f;
#pragma unroll
        for (int c = 0; c < 32; c++) tm = fmaxf(tm, Cs[r * CP + c0 + c]);
        tm = fmaxf(tm, __shfl_xor_sync(0xffffffffu, tm, 1, 4));
        tm = fmaxf(tm, __shfl_xor_sync(0xffffffffu, tm, 2, 4));
        if ((tid & 3) == 0) atomicMax(&rm[r], enc_f(tm));
        __syncthreads();

        const float thr = dec_f(rm[r]) - 0.5f;
        const int m0 = mt * 128;
#pragma unroll
        for (int c = 0; c < 32; c++) {
            const float v = Cs[r * CP + c0 + c];
            if (v >= thr) {
                int pos = atomicAdd(&cnt[r], 1);
                if (pos < CAND) {
                    cm[r * CAND + pos]  = m0 + c0 + c;
                    csv[r * CAND + pos] = v;
                }
            }
        }
        __syncthreads();
    }

    if (tid < 64) {
        const float fmax = dec_f(rm[tid]);
        const float thrF = fmax - 0.5f;
        const int nc = cnt[tid] < CAND ? cnt[tid] : CAND;
        int hits = 0;
        for (int j = 0; j < nc; j++) {
            if (csv[tid * CAND + j] >= thrF) {
                cm[tid * CAND + hits] = cm[tid * CAND + j];
                hits++;
            }
        }
        cnt[tid] = hits;
        wrow[tid] = (fabsf(fmax) > 0.5f && hits > 0) ? 1.f / (float)hits : 0.f;
    }
    __syncthreads();

    // scatter: warp-per-row; Yt row is contiguous -> coalesced preload
    const float* Yh = Yt + (size_t)h * Nc * Dc;
    for (int rr = 0; rr < 8; rr++) {
        const int r = w * 8 + rr;
        const float wv = wrow[r];
        const int hits = cnt[r];
        if (wv == 0.f || hits == 0) continue;
        const int n = r0 + r;
        const float* yrow = Yh + (size_t)n * Dc;
        float yv[16];
#pragma unroll
        for (int p = 0; p < 16; p++)
            yv[p] = wv * yrow[lane + p * 32];
        for (int j = 0; j < hits; j++) {
            const int m = cm[r * CAND + j];
#pragma unroll
            for (int p = 0; p < 16; p++)
                atomicAdd(&attn[(size_t)(lane + p * 32) * Nc + m], yv[p]);
        }
    }
}

// --------------------------------------------------------------------------
extern "C" void kernel_launch(void* const* d_in, const int* in_sizes, int n_in,
                              void* d_out, int out_size)
{
    const float* X  = (const float*)d_in[0];
    const float* Kp = (const float*)d_in[1];
    const float* Vp = (const float*)d_in[2];
    const float* W1 = (const float*)d_in[3];
    const float* b1 = (const float*)d_in[4];
    const float* W2 = (const float*)d_in[5];
    const float* b2 = (const float*)d_in[6];

    float *gX, *gAttn, *gY;
    __nv_bfloat16 *gKVh, *gKVl, *gW1h, *gW1l, *gW2h, *gW2l;
    __nv_bfloat16 *gXh, *gXl, *gAth, *gAtl, *gF1h, *gF1l, *gKXh, *gKXl;
    cudaGetSymbolAddress((void**)&gX,   g_X);
    cudaGetSymbolAddress((void**)&gAttn,g_attn);
    cudaGetSymbolAddress((void**)&gY,   g_Y);
    cudaGetSymbolAddress((void**)&gKVh, g_KVh);  cudaGetSymbolAddress((void**)&gKVl, g_KVl);
    cudaGetSymbolAddress((void**)&gW1h, g_W1h);  cudaGetSymbolAddress((void**)&gW1l, g_W1l);
    cudaGetSymbolAddress((void**)&gW2h, g_W2h);  cudaGetSymbolAddress((void**)&gW2l, g_W2l);
    cudaGetSymbolAddress((void**)&gXh,  g_Xh);   cudaGetSymbolAddress((void**)&gXl,  g_Xl);
    cudaGetSymbolAddress((void**)&gAth, g_Ath);  cudaGetSymbolAddress((void**)&gAtl, g_Atl);
    cudaGetSymbolAddress((void**)&gF1h, g_F1h);  cudaGetSymbolAddress((void**)&gF1l, g_F1l);
    cudaGetSymbolAddress((void**)&gKXh, g_KXh);  cudaGetSymbolAddress((void**)&gKXl, g_KXl);

    const int SMY  = 4 * (2 * 128 * 40 * 2 + 2 * 32 * 264 * 2);   // 217088
    const int SMF2 = 4 * (2 *  64 * 40 * 2 + 2 * 32 * 136 * 2);   // 110592
    const int SMGR = 171776;
    cudaFuncSetAttribute(bf16_gemm<128, 256, 2, 4, 4>,
                         cudaFuncAttributeMaxDynamicSharedMemorySize, SMY);
    cudaFuncSetAttribute(bf16_gemm<64, 128, 2, 4, 4>,
                         cudaFuncAttributeMaxDynamicSharedMemorySize, SMF2);
    cudaFuncSetAttribute(gram_argmax_scatter,
                         cudaFuncAttributeMaxDynamicSharedMemorySize, SMGR);

    {
        const int nW  = Lc * DFFc * Dc / 4;
        const int nX  = Dc * Nc / 4;
        const int nKV = Lc * KVROWS * Dc / 4;
        pack_kv<<<(nKV + 255) / 256, 256>>>((const float4*)Vp, (const float4*)Kp,
                                            gKVh, gKVl);
        split_kernel<<<(nW + 255) / 256, 256>>>((const float4*)W1, gW1h, gW1l, nullptr, nW);
        split_kernel<<<(nW + 255) / 256, 256>>>((const float4*)W2, gW2h, gW2l, nullptr, nW);
        // X split also seeds attn = X for layer 0
        split_kernel<<<(nX + 255) / 256, 256>>>((const float4*)X, gXh, gXl,
                                                (float4*)gAttn, nX);
    }

    for (int l = 0; l < Lc; l++) {
        const float* b1l = b1 + (size_t)l * DFFc;
        const float* b2l = b2 + (size_t)l * Dc;
        const bool last = (l == Lc - 1);

        // 1) [Yt; KX] = [V_l; K_l] @ X  (merged, mode 64, 144 blocks = 1 wave)
        bf16_gemm<128, 256, 2, 4, 4><<<dim3(Nc / 256, KVROWS / 128, 1), 256, SMY>>>(
            gKVh + (size_t)l * KVROWS * Dc, gKVl + (size_t)l * KVROWS * Dc,
            gXh, gXl, gY, nullptr, gKXh, gKXl,
            KVROWS, Nc, Dc, 0, 0, nullptr, nullptr, 64);

        // 2) fused gram+argmax+scatter: attn (already = X) += scatter
        gram_argmax_scatter<<<dim3(Nc / 64, Hc), 256, SMGR>>>(gKXh, gKXl, gY, gAttn);

        // 3) attn planes
        split_kernel<<<(Dc * Nc / 4 + 255) / 256, 256>>>(
            (const float4*)gAttn, gAth, gAtl, nullptr, Dc * Nc / 4);

        // 4) ff1 planes = relu(W1_l @ attn + b1)  (mode 9)
        bf16_gemm<128, 256, 2, 4, 4><<<dim3(Nc / 256, DFFc / 128, 1), 256, SMY>>>(
            gW1h + (size_t)l * DFFc * Dc, gW1l + (size_t)l * DFFc * Dc,
            gAth, gAtl, nullptr, nullptr, gF1h, gF1l,
            DFFc, Nc, Dc, 0, 0, b1l, nullptr, 9);

        // 5) X = attn + W2_l @ ff1 + b2
        if (last) {
            bf16_gemm<64, 128, 2, 4, 4><<<dim3(Nc / 128, Dc / 64, 1), 256, SMF2>>>(
                gW2h + (size_t)l * Dc * DFFc, gW2l + (size_t)l * Dc * DFFc,
                gF1h, gF1l, (float*)d_out, nullptr, nullptr, nullptr,
                Dc, Nc, DFFc, 0, 0, b2l, gAttn, 6);
        } else {
            bf16_gemm<64, 128, 2, 4, 4><<<dim3(Nc / 128, Dc / 64, 1), 256, SMF2>>>(
                gW2h + (size_t)l * Dc * DFFc, gW2l + (size_t)l * Dc * DFFc,
                gF1h, gF1l, gX, gAttn, gXh, gXl,
                Dc, Nc, DFFc, 0, 0, b2l, gAttn, 46);
        }
    }
}

// round 13
// speedup vs baseline: 1.1496x; 1.0472x over previous
#include <cuda_runtime.h>
#include <cuda_bf16.h>
#include <mma.h>
#include <cstdint>

using namespace nvcuda;

#define Lc   8
#define Hc   4
#define Qc   64
#define Dc   512
#define Nc   2048
#define DFFc 2048
#define KVROWS (Hc * Dc + Hc * Qc)   // 2304 output cols: Y then KX
#define YROWS  (Hc * Dc)             // 2048

// ---------------- device scratch (no allocations allowed) ----------------
// All activations N-major: acts[n][feature]
__device__ float g_X[Nc * Dc];                        // X_t staging (last layer)
__device__ float g_attn[Nc * Dc];                     // attn_t[n][d]
__device__ float g_Y[Nc * YROWS];                     // Y[n][h*512+d]
__device__ __nv_bfloat16 g_KVh[Lc * Dc * KVROWS], g_KVl[Lc * Dc * KVROWS]; // KV^T
__device__ __nv_bfloat16 g_W1h[Lc * Dc * DFFc],   g_W1l[Lc * Dc * DFFc];   // W1^T
__device__ __nv_bfloat16 g_W2h[Lc * DFFc * Dc],   g_W2l[Lc * DFFc * Dc];   // W2^T
__device__ __nv_bfloat16 g_Xh[Nc * Dc],           g_Xl[Nc * Dc];           // Xt planes
__device__ __nv_bfloat16 g_Ath[Nc * Dc],          g_Atl[Nc * Dc];          // attn_t planes
__device__ __nv_bfloat16 g_F1h[Nc * DFFc],        g_F1l[Nc * DFFc];        // ff1_t planes
__device__ __nv_bfloat16 g_KXh[Nc * 256],         g_KXl[Nc * 256];         // KXt planes

// ---------------- helpers --------------------------------------------------
__device__ __forceinline__ uint32_t smem_u32(const void* p) {
    uint32_t a;
    asm("{ .reg .u64 t; cvta.to.shared.u64 t, %1; cvt.u32.u64 %0, t; }"
        : "=r"(a) : "l"(p));
    return a;
}
__device__ __forceinline__ void cp16(void* s, const void* g) {
    asm volatile("cp.async.cg.shared.global [%0], [%1], 16;"
                 :: "r"(smem_u32(s)), "l"(g) : "memory");
}
__device__ __forceinline__ void cp_commit() {
    asm volatile("cp.async.commit_group;" ::: "memory");
}
template<int N> __device__ __forceinline__ void cp_wait() {
    asm volatile("cp.async.wait_group %0;" :: "n"(N) : "memory");
}

__device__ __forceinline__ void split_store4(__nv_bfloat16* __restrict__ Hd,
                                             __nv_bfloat16* __restrict__ Ld,
                                             float4 v)
{
    __nv_bfloat162 h0 = __floats2bfloat162_rn(v.x, v.y);
    __nv_bfloat162 h1 = __floats2bfloat162_rn(v.z, v.w);
    float2 f0 = __bfloat1622float2(h0);
    float2 f1 = __bfloat1622float2(h1);
    __nv_bfloat162 l0 = __floats2bfloat162_rn(v.x - f0.x, v.y - f0.y);
    __nv_bfloat162 l1 = __floats2bfloat162_rn(v.z - f1.x, v.w - f1.y);
    *(__nv_bfloat162*)(Hd)     = h0;
    *(__nv_bfloat162*)(Hd + 2) = h1;
    *(__nv_bfloat162*)(Ld)     = l0;
    *(__nv_bfloat162*)(Ld + 2) = l1;
}
__device__ __forceinline__ void split1s(float v, __nv_bfloat16* H, __nv_bfloat16* L) {
    __nv_bfloat16 hv = __float2bfloat16(v);
    *H = hv;
    *L = __float2bfloat16(v - __bfloat162float(hv));
}

__device__ __forceinline__ unsigned enc_f(float f) {
    unsigned u = __float_as_uint(f);
    return (u & 0x80000000u) ? ~u : (u | 0x80000000u);
}
__device__ __forceinline__ float dec_f(unsigned v) {
    return __uint_as_float((v & 0x80000000u) ? (v ^ 0x80000000u) : ~v);
}

// ---------------- plain split (no transpose) -------------------------------
__global__ void __launch_bounds__(256) split_kernel(
    const float4* __restrict__ src,
    __nv_bfloat16* __restrict__ h, __nv_bfloat16* __restrict__ l, int n4)
{
    int i = blockIdx.x * 256 + threadIdx.x;
    if (i < n4) {
        float4 v = src[i];
        split_store4(h + (size_t)i * 4, l + (size_t)i * 4, v);
    }
}

// ---------------- smem-tiled transpose + split ------------------------------
// src: batch of [R][C] row-major fp32. dst planes: [C][R] (pitch R), batch
// stride R*C. Optional fp32 transposed copy.
__global__ void __launch_bounds__(256) tsplit_generic(
    const float* __restrict__ src,
    __nv_bfloat16* __restrict__ dH, __nv_bfloat16* __restrict__ dL,
    float* __restrict__ copyT, int R, int C)
{
    __shared__ float t[32][33];
    const size_t bo = (size_t)blockIdx.z * R * C;
    const int tx = threadIdx.x, ty = threadIdx.y;
    const int x  = blockIdx.x * 32 + tx;       // src col (-> dst row)
    const int y0 = blockIdx.y * 32;            // src row (-> dst col)
#pragma unroll
    for (int j = 0; j < 4; j++)
        t[ty + j * 8][tx] = src[bo + (size_t)(y0 + ty + j * 8) * C + x];
    __syncthreads();
#pragma unroll
    for (int j = 0; j < 4; j++) {
        const int k = blockIdx.x * 32 + ty + j * 8;
        const int r = y0 + tx;
        const float v = t[tx][ty + j * 8];
        const size_t di = bo + (size_t)k * R + r;
        split1s(v, dH + di, dL + di);
        if (copyT) copyT[di] = v;
    }
}

// ---------------- KV^T pack: V[l][h][dout][k], K[l][h][q][k] ---------------
// dst[l]: [512 rows k][2304 cols], V cols h*512+dout, K cols 2048+h*64+q
__global__ void __launch_bounds__(256) tsplit_kv(
    const float* __restrict__ src,
    __nv_bfloat16* __restrict__ dH, __nv_bfloat16* __restrict__ dL,
    int R, int colOff0, int colUnit)
{
    __shared__ float t[32][33];
    const int b = blockIdx.z, l = b >> 2, h = b & 3;
    const float* s = src + (size_t)b * R * Dc;
    const size_t dbase = (size_t)l * Dc * KVROWS + colOff0 + h * colUnit;
    const int tx = threadIdx.x, ty = threadIdx.y;
    const int x  = blockIdx.x * 32 + tx;       // k
    const int y0 = blockIdx.y * 32;            // r (dout / q)
#pragma unroll
    for (int j = 0; j < 4; j++)
        t[ty + j * 8][tx] = s[(size_t)(y0 + ty + j * 8) * Dc + x];
    __syncthreads();
#pragma unroll
    for (int j = 0; j < 4; j++) {
        const int k = blockIdx.x * 32 + ty + j * 8;
        const int r = y0 + tx;
        const float v = t[tx][ty + j * 8];
        const size_t di = dbase + (size_t)k * KVROWS + r;
        split1s(v, dH + di, dL + di);
    }
}

// ---------------- final transpose: Xt[n][d] -> out[d][n] --------------------
__global__ void __launch_bounds__(256) tfinal(
    const float* __restrict__ Xt, float* __restrict__ out)
{
    __shared__ float t[32][33];
    const int tx = threadIdx.x, ty = threadIdx.y;
    const int x  = blockIdx.x * 32 + tx;       // d
    const int y0 = blockIdx.y * 32;            // n
#pragma unroll
    for (int j = 0; j < 4; j++)
        t[ty + j * 8][tx] = Xt[(size_t)(y0 + ty + j * 8) * Dc + x];
    __syncthreads();
#pragma unroll
    for (int j = 0; j < 4; j++) {
        const int d = blockIdx.x * 32 + ty + j * 8;
        const int n = y0 + tx;
        out[(size_t)d * Nc + n] = t[tx][ty + j * 8];
    }
}

// ============ bf16-plane 3x GEMM (acts @ weight^T), cp.async pipeline ======
// A:[M,K] act planes, B:[K,N] weight^T planes, row-major bf16.
// mode bits: 1=relu(+col bias), 2=residual(+col bias), 4=write fp32 C,
//            8=write h+l planes.
// mode==64 -> KV: cols < YROWS direct fp32 store into C (pitch YROWS);
//             cols >= YROWS emit h/l planes (pitch 256) at col-YROWS.
template<int BM, int BN, int WM, int WN, int S>
__global__ void __launch_bounds__(WM * WN * 32) bf16_gemm(
    const __nv_bfloat16* __restrict__ Ah, const __nv_bfloat16* __restrict__ Al,
    const __nv_bfloat16* __restrict__ Bh, const __nv_bfloat16* __restrict__ Bl,
    float* __restrict__ C,
    __nv_bfloat16* __restrict__ Ch, __nv_bfloat16* __restrict__ Cl,
    int M, int N, int K,
    const float* __restrict__ bias, const float* __restrict__ R, int mode)
{
    constexpr int TH = WM * WN * 32;
    constexpr int BK = 32;
    constexpr int AP = 40;
    constexpr int BP = BN + 8;
    constexpr int ABYT = BM * AP * 2;
    constexpr int BBYT = BK * BP * 2;
    constexpr int STG = 2 * ABYT + 2 * BBYT;
    constexpr int MF = BM / (WM * 16);
    constexpr int NF = BN / (WN * 16);
    constexpr int AIT = BM * (BK / 8) / TH;
    constexpr int BIT = BK * (BN / 8) / TH;

    extern __shared__ char sm[];
    const int tid = threadIdx.x, w = tid >> 5;
    const int bm = blockIdx.y * BM;
    const int bn = blockIdx.x * BN;
    const int wm0 = (w % WM) * (MF * 16);
    const int wn0 = (w / WM) * (NF * 16);
    const int KT = K / BK;

    auto issue = [&](int tile) {
        const int k0 = tile * BK;
        char* st = sm + (tile % S) * STG;
        __nv_bfloat16* sAh = (__nv_bfloat16*)st;
        __nv_bfloat16* sAl = (__nv_bfloat16*)(st + ABYT);
        __nv_bfloat16* sBh = (__nv_bfloat16*)(st + 2 * ABYT);
        __nv_bfloat16* sBl = (__nv_bfloat16*)(st + 2 * ABYT + BBYT);
#pragma unroll
        for (int p = 0; p < AIT; p++) {
            const int c = tid + p * TH;
            const int r = c >> 2, c8 = (c & 3) * 8;
            cp16(sAh + r * AP + c8, Ah + (size_t)(bm + r) * K + k0 + c8);
            cp16(sAl + r * AP + c8, Al + (size_t)(bm + r) * K + k0 + c8);
        }
#pragma unroll
        for (int p = 0; p < BIT; p++) {
            const int c = tid + p * TH;
            const int r = c / (BN / 8), c8 = (c % (BN / 8)) * 8;
            cp16(sBh + r * BP + c8, Bh + (size_t)(k0 + r) * N + bn + c8);
            cp16(sBl + r * BP + c8, Bl + (size_t)(k0 + r) * N + bn + c8);
        }
    };

    wmma::fragment<wmma::accumulator, 16, 16, 16, float> acc[MF][NF];
#pragma unroll
    for (int i = 0; i < MF; i++)
#pragma unroll
        for (int j = 0; j < NF; j++) wmma::fill_fragment(acc[i][j], 0.f);

#pragma unroll
    for (int t = 0; t < S - 1; t++) {
        if (t < KT) issue(t);
        cp_commit();
    }

#pragma unroll 1
    for (int kt = 0; kt < KT; kt++) {
        cp_wait<S - 2>();
        __syncthreads();
        if (kt + S - 1 < KT) issue(kt + S - 1);
        cp_commit();

        char* st = sm + (kt % S) * STG;
        const __nv_bfloat16* sAh = (const __nv_bfloat16*)st;
        const __nv_bfloat16* sAl = (const __nv_bfloat16*)(st + ABYT);
        const __nv_bfloat16* sBh = (const __nv_bfloat16*)(st + 2 * ABYT);
        const __nv_bfloat16* sBl = (const __nv_bfloat16*)(st + 2 * ABYT + BBYT);

#pragma unroll
        for (int kks = 0; kks < 2; kks++) {
            const int kk = kks * 16;
            wmma::fragment<wmma::matrix_a, 16, 16, 16, __nv_bfloat16, wmma::row_major> fAh[MF];
            wmma::fragment<wmma::matrix_b, 16, 16, 16, __nv_bfloat16, wmma::row_major> fBh[NF];
#pragma unroll
            for (int i = 0; i < MF; i++)
                wmma::load_matrix_sync(fAh[i], sAh + (wm0 + i * 16) * AP + kk, AP);
#pragma unroll
            for (int j = 0; j < NF; j++)
                wmma::load_matrix_sync(fBh[j], sBh + kk * BP + wn0 + j * 16, BP);
#pragma unroll
            for (int i = 0; i < MF; i++)
#pragma unroll
                for (int j = 0; j < NF; j++)
                    wmma::mma_sync(acc[i][j], fAh[i], fBh[j], acc[i][j]);
            {
                wmma::fragment<wmma::matrix_b, 16, 16, 16, __nv_bfloat16, wmma::row_major> fBl[NF];
#pragma unroll
                for (int j = 0; j < NF; j++)
                    wmma::load_matrix_sync(fBl[j], sBl + kk * BP + wn0 + j * 16, BP);
#pragma unroll
                for (int i = 0; i < MF; i++)
#pragma unroll
                    for (int j = 0; j < NF; j++)
                        wmma::mma_sync(acc[i][j], fAh[i], fBl[j], acc[i][j]);
            }
            {
                wmma::fragment<wmma::matrix_a, 16, 16, 16, __nv_bfloat16, wmma::row_major> fAl[MF];
#pragma unroll
                for (int i = 0; i < MF; i++)
                    wmma::load_matrix_sync(fAl[i], sAl + (wm0 + i * 16) * AP + kk, AP);
#pragma unroll
                for (int i = 0; i < MF; i++)
#pragma unroll
                    for (int j = 0; j < NF; j++)
                        wmma::mma_sync(acc[i][j], fAl[i], fBh[j], acc[i][j]);
            }
        }
    }

    if (mode == 64) {
        if (bn < YROWS) {
            // Y region: natural row-major store, pitch YROWS
#pragma unroll
            for (int i = 0; i < MF; i++)
#pragma unroll
                for (int j = 0; j < NF; j++)
                    wmma::store_matrix_sync(
                        &C[(size_t)(bm + wm0 + i * 16) * YROWS + bn + wn0 + j * 16],
                        acc[i][j], YROWS, wmma::mem_row_major);
        } else {
            // KX region: stage, split to planes (pitch 256)
            __syncthreads();
            float* cs = (float*)sm;
#pragma unroll
            for (int i = 0; i < MF; i++)
#pragma unroll
                for (int j = 0; j < NF; j++)
                    wmma::store_matrix_sync(
                        cs + (size_t)(wm0 + i * 16) * BN + wn0 + j * 16,
                        acc[i][j], BN, wmma::mem_row_major);
            __syncthreads();
            constexpr int CIT2 = BM * BN / 4 / TH;
#pragma unroll
            for (int p = 0; p < CIT2; p++) {
                const int id = tid + p * TH;
                const int row = id / (BN / 4), c4 = id % (BN / 4);
                float4 v = ((const float4*)cs)[id];
                const int gr = bm + row;
                const int gcl = c4 * 4;
                split_store4(Ch + (size_t)gr * 256 + gcl,
                             Cl + (size_t)gr * 256 + gcl, v);
            }
        }
        return;
    }

    __syncthreads();
    float* cs = (float*)sm;
#pragma unroll
    for (int i = 0; i < MF; i++)
#pragma unroll
        for (int j = 0; j < NF; j++)
            wmma::store_matrix_sync(cs + (size_t)(wm0 + i * 16) * BN + wn0 + j * 16,
                                    acc[i][j], BN, wmma::mem_row_major);
    __syncthreads();

    constexpr int CIT = BM * BN / 4 / TH;
#pragma unroll
    for (int p = 0; p < CIT; p++) {
        const int id = tid + p * TH;
        const int row = id / (BN / 4), c4 = id % (BN / 4);
        float4 v = ((const float4*)cs)[id];
        const int gr = bm + row;
        const int gc = bn + c4 * 4;
        if (mode & 3) {
            float4 bv = *(const float4*)&bias[gc];   // column bias
            v.x += bv.x; v.y += bv.y; v.z += bv.z; v.w += bv.w;
        }
        if (mode & 1) {
            v.x = fmaxf(v.x, 0.f); v.y = fmaxf(v.y, 0.f);
            v.z = fmaxf(v.z, 0.f); v.w = fmaxf(v.w, 0.f);
        }
        if (mode & 2) {
            float4 r4 = *(const float4*)&R[(size_t)gr * N + gc];
            v.x += r4.x; v.y += r4.y; v.z += r4.z; v.w += r4.w;
        }
        if (mode & 4) *(float4*)&C[(size_t)gr * N + gc] = v;
        if (mode & 8) split_store4(Ch + (size_t)gr * N + gc,
                                   Cl + (size_t)gr * N + gc, v);
    }
}

// ====== fused gram + argmax + scatter (N-major, coalesced scatter) =========
// KXt[n][h*64+q] planes; Y[n][h*512+d]; attn_t[n][d].
#define CAND 96
__global__ void __launch_bounds__(256) gram_argmax_scatter(
    const __nv_bfloat16* __restrict__ KXh, const __nv_bfloat16* __restrict__ KXl,
    const float* __restrict__ Y, float* __restrict__ attn)
{
    constexpr int AP = 72, BP = 72, CP = 132;
    extern __shared__ char sm[];
    __nv_bfloat16* aH = (__nv_bfloat16*)sm;                  // 9216
    __nv_bfloat16* aL = (__nv_bfloat16*)(sm + 9216);         // 9216
    // B stages at 18432: stage s at 18432 + s*36864 (bH 18432, bL 18432)
    float*    Cs   = (float*)(sm + 92160);                   // 33792
    unsigned* rm   = (unsigned*)(sm + 125952);
    int*      cnt  = (int*)(sm + 126208);
    float*    wrow = (float*)(sm + 126464);
    int*      cm   = (int*)(sm + 126720);                    // 24576
    float*    csv  = (float*)(sm + 151296);                  // 24576 -> 175872

    const int h  = blockIdx.y;
    const int r0 = blockIdx.x * 64;
    const int co = h * 64;                                   // col offset in KXt
    const int tid = threadIdx.x, w = tid >> 5, lane = tid & 31;
    const int wm0 = (w & 1) * 32, wn0 = (w >> 1) * 32;

    if (tid < 64) { rm[tid] = enc_f(-1e30f); cnt[tid] = 0; }

    auto issueB = [&](int mt, int s) {
        const int m0 = mt * 128;
        __nv_bfloat16* bH = (__nv_bfloat16*)(sm + 18432 + s * 36864);
        __nv_bfloat16* bL = (__nv_bfloat16*)(sm + 18432 + s * 36864 + 18432);
#pragma unroll
        for (int p = 0; p < 4; p++) {
            const int c = tid + p * 256;
            const int r = c >> 3, c8 = (c & 7) * 8;
            cp16(bH + r * BP + c8, KXh + (size_t)(m0 + r) * 256 + co + c8);
            cp16(bL + r * BP + c8, KXl + (size_t)(m0 + r) * 256 + co + c8);
        }
    };

    // A stripe: rows r0..r0+63, 64 cols (contiguous 128B per row)
#pragma unroll
    for (int p = 0; p < 2; p++) {
        const int c = tid + p * 256;
        const int r = c >> 3, c8 = (c & 7) * 8;
        cp16(aH + r * AP + c8, KXh + (size_t)(r0 + r) * 256 + co + c8);
        cp16(aL + r * AP + c8, KXl + (size_t)(r0 + r) * 256 + co + c8);
    }
    issueB(0, 0);
    cp_commit();

    for (int mt = 0; mt < Nc / 128; mt++) {
        if (mt + 1 < Nc / 128) issueB(mt + 1, (mt + 1) & 1);
        cp_commit();
        cp_wait<1>();
        __syncthreads();

        const __nv_bfloat16* bH = (const __nv_bfloat16*)(sm + 18432 + (mt & 1) * 36864);
        const __nv_bfloat16* bL = bH + 18432 / 2;

        wmma::fragment<wmma::accumulator, 16, 16, 16, float> acc[2][2];
#pragma unroll
        for (int i = 0; i < 2; i++)
#pragma unroll
            for (int j = 0; j < 2; j++) wmma::fill_fragment(acc[i][j], 0.f);

#pragma unroll
        for (int kks = 0; kks < 4; kks++) {
            const int kk = kks * 16;
            // A: rows n (stripe) x cols q -> row_major; B: rows m x cols q -> col_major
            wmma::fragment<wmma::matrix_a, 16, 16, 16, __nv_bfloat16, wmma::row_major> fAh[2];
            wmma::fragment<wmma::matrix_b, 16, 16, 16, __nv_bfloat16, wmma::col_major> fBh[2];
#pragma unroll
            for (int i = 0; i < 2; i++)
                wmma::load_matrix_sync(fAh[i], aH + (wm0 + i * 16) * AP + kk, AP);
#pragma unroll
            for (int j = 0; j < 2; j++)
                wmma::load_matrix_sync(fBh[j], bH + (wn0 + j * 16) * BP + kk, BP);
#pragma unroll
            for (int i = 0; i < 2; i++)
#pragma unroll
                for (int j = 0; j < 2; j++)
                    wmma::mma_sync(acc[i][j], fAh[i], fBh[j], acc[i][j]);
            {
                wmma::fragment<wmma::matrix_b, 16, 16, 16, __nv_bfloat16, wmma::col_major> fBl[2];
#pragma unroll
                for (int j = 0; j < 2; j++)
                    wmma::load_matrix_sync(fBl[j], bL + (wn0 + j * 16) * BP + kk, BP);
#pragma unroll
                for (int i = 0; i < 2; i++)
#pragma unroll
                    for (int j = 0; j < 2; j++)
                        wmma::mma_sync(acc[i][j], fAh[i], fBl[j], acc[i][j]);
            }
            {
                wmma::fragment<wmma::matrix_a, 16, 16, 16, __nv_bfloat16, wmma::row_major> fAl[2];
#pragma unroll
                for (int i = 0; i < 2; i++)
                    wmma::load_matrix_sync(fAl[i], aL + (wm0 + i * 16) * AP + kk, AP);
#pragma unroll
                for (int i = 0; i < 2; i++)
#pragma unroll
                    for (int j = 0; j < 2; j++)
                        wmma::mma_sync(acc[i][j], fAl[i], fBh[j], acc[i][j]);
            }
        }
#pragma unroll
        for (int i = 0; i < 2; i++)
#pragma unroll
            for (int j = 0; j < 2; j++)
                wmma::store_matrix_sync(Cs + (wm0 + i * 16) * CP + wn0 + j * 16,
                                        acc[i][j], CP, wmma::mem_row_major);
        __syncthreads();

        const int r = tid >> 2;
        const int c0 = (tid & 3) * 32;
        float tm = -1e30f;
#pragma unroll
        for (int c = 0; c < 32; c++) tm = fmaxf(tm, Cs[r * CP + c0 + c]);
        tm = fmaxf(tm, __shfl_xor_sync(0xffffffffu, tm, 1, 4));
        tm = fmaxf(tm, __shfl_xor_sync(0xffffffffu, tm, 2, 4));
        if ((tid & 3) == 0) atomicMax(&rm[r], enc_f(tm));
        __syncthreads();

        const float thr = dec_f(rm[r]) - 0.5f;
        const int m0 = mt * 128;
#pragma unroll
        for (int c = 0; c < 32; c++) {
            const float v = Cs[r * CP + c0 + c];
            if (v >= thr) {
                int pos = atomicAdd(&cnt[r], 1);
                if (pos < CAND) {
                    cm[r * CAND + pos]  = m0 + c0 + c;
                    csv[r * CAND + pos] = v;
                }
            }
        }
        __syncthreads();
    }

    if (tid < 64) {
        const float fmax = dec_f(rm[tid]);
        const float thrF = fmax - 0.5f;
        const int nc = cnt[tid] < CAND ? cnt[tid] : CAND;
        int hits = 0;
        for (int j = 0; j < nc; j++) {
            if (csv[tid * CAND + j] >= thrF) {
                cm[tid * CAND + hits] = cm[tid * CAND + j];
                hits++;
            }
        }
        cnt[tid] = hits;
        wrow[tid] = (fabsf(fmax) > 0.5f && hits > 0) ? 1.f / (float)hits : 0.f;
    }
    __syncthreads();

    // scatter: warp-per-row; Y row contiguous, attn_t row contiguous atomics
    for (int rr = 0; rr < 8; rr++) {
        const int r = w * 8 + rr;
        const float wv = wrow[r];
        const int hits = cnt[r];
        if (wv == 0.f || hits == 0) continue;
        const int n = r0 + r;
        const float* yrow = Y + (size_t)n * YROWS + h * Dc;
        float yv[16];
#pragma unroll
        for (int p = 0; p < 16; p++)
            yv[p] = wv * yrow[lane + p * 32];
        for (int j = 0; j < hits; j++) {
            float* arow = attn + (size_t)cm[r * CAND + j] * Dc;
#pragma unroll
            for (int p = 0; p < 16; p++)
                atomicAdd(&arow[lane + p * 32], yv[p]);
        }
    }
}

// --------------------------------------------------------------------------
extern "C" void kernel_launch(void* const* d_in, const int* in_sizes, int n_in,
                              void* d_out, int out_size)
{
    const float* X  = (const float*)d_in[0];
    const float* Kp = (const float*)d_in[1];
    const float* Vp = (const float*)d_in[2];
    const float* W1 = (const float*)d_in[3];
    const float* b1 = (const float*)d_in[4];
    const float* W2 = (const float*)d_in[5];
    const float* b2 = (const float*)d_in[6];

    float *gX, *gAttn, *gY;
    __nv_bfloat16 *gKVh, *gKVl, *gW1h, *gW1l, *gW2h, *gW2l;
    __nv_bfloat16 *gXh, *gXl, *gAth, *gAtl, *gF1h, *gF1l, *gKXh, *gKXl;
    cudaGetSymbolAddress((void**)&gX,   g_X);
    cudaGetSymbolAddress((void**)&gAttn,g_attn);
    cudaGetSymbolAddress((void**)&gY,   g_Y);
    cudaGetSymbolAddress((void**)&gKVh, g_KVh);  cudaGetSymbolAddress((void**)&gKVl, g_KVl);
    cudaGetSymbolAddress((void**)&gW1h, g_W1h);  cudaGetSymbolAddress((void**)&gW1l, g_W1l);
    cudaGetSymbolAddress((void**)&gW2h, g_W2h);  cudaGetSymbolAddress((void**)&gW2l, g_W2l);
    cudaGetSymbolAddress((void**)&gXh,  g_Xh);   cudaGetSymbolAddress((void**)&gXl,  g_Xl);
    cudaGetSymbolAddress((void**)&gAth, g_Ath);  cudaGetSymbolAddress((void**)&gAtl, g_Atl);
    cudaGetSymbolAddress((void**)&gF1h, g_F1h);  cudaGetSymbolAddress((void**)&gF1l, g_F1l);
    cudaGetSymbolAddress((void**)&gKXh, g_KXh);  cudaGetSymbolAddress((void**)&gKXl, g_KXl);

    const int SMY  = 4 * (2 * 128 * 40 * 2 + 2 * 32 * 264 * 2);   // 217088
    const int SMF2 = 4 * (2 *  64 * 40 * 2 + 2 * 32 * 136 * 2);   // 110592
    const int SMGR = 175872;
    cudaFuncSetAttribute(bf16_gemm<128, 256, 2, 4, 4>,
                         cudaFuncAttributeMaxDynamicSharedMemorySize, SMY);
    cudaFuncSetAttribute(bf16_gemm<64, 128, 2, 4, 4>,
                         cudaFuncAttributeMaxDynamicSharedMemorySize, SMF2);
    cudaFuncSetAttribute(gram_argmax_scatter,
                         cudaFuncAttributeMaxDynamicSharedMemorySize, SMGR);

    {
        dim3 blk(32, 8);
        // KV^T: V -> cols [h*512, h*512+512), K -> cols [2048+h*64, ...)
        tsplit_kv<<<dim3(16, 16, Lc * Hc), blk>>>(Vp, gKVh, gKVl, Dc, 0, Dc);
        tsplit_kv<<<dim3(16, 2,  Lc * Hc), blk>>>(Kp, gKVh, gKVl, Qc, YROWS, Qc);
        // W1^T: [2048][512] -> [512][2048]
        tsplit_generic<<<dim3(512 / 32, 2048 / 32, Lc), blk>>>(
            W1, gW1h, gW1l, nullptr, DFFc, Dc);
        // W2^T: [512][2048] -> [2048][512]
        tsplit_generic<<<dim3(2048 / 32, 512 / 32, Lc), blk>>>(
            W2, gW2h, gW2l, nullptr, Dc, DFFc);
        // X: [512][2048] -> Xt [2048][512] planes + attn_t fp32 seed
        tsplit_generic<<<dim3(2048 / 32, 512 / 32, 1), blk>>>(
            X, gXh, gXl, gAttn, Dc, Nc);
    }

    for (int l = 0; l < Lc; l++) {
        const float* b1l = b1 + (size_t)l * DFFc;
        const float* b2l = b2 + (size_t)l * Dc;
        const bool last = (l == Lc - 1);

        // 1) [Y | KXt] = Xt @ KV^T  (mode 64, grid 9x16 = 144 blocks)
        bf16_gemm<128, 256, 2, 4, 4><<<dim3(KVROWS / 256, Nc / 128, 1), 256, SMY>>>(
            gXh, gXl,
            gKVh + (size_t)l * Dc * KVROWS, gKVl + (size_t)l * Dc * KVROWS,
            gY, gKXh, gKXl, Nc, KVROWS, Dc, nullptr, nullptr, 64);

        // 2) fused gram+argmax+scatter: attn_t (already = X_t) += scatter
        gram_argmax_scatter<<<dim3(Nc / 64, Hc), 256, SMGR>>>(gKXh, gKXl, gY, gAttn);

        // 3) attn_t planes
        split_kernel<<<(Nc * Dc / 4 + 255) / 256, 256>>>(
            (const float4*)gAttn, gAth, gAtl, Nc * Dc / 4);

        // 4) ff1_t planes = relu(attn_t @ W1^T + b1[col])  (mode 9)
        bf16_gemm<128, 256, 2, 4, 4><<<dim3(DFFc / 256, Nc / 128, 1), 256, SMY>>>(
            gAth, gAtl,
            gW1h + (size_t)l * Dc * DFFc, gW1l + (size_t)l * Dc * DFFc,
            nullptr, gF1h, gF1l, Nc, DFFc, Dc, b1l, nullptr, 9);

        // 5) X_t = attn_t + ff1_t @ W2^T + b2[col]
        if (last) {
            bf16_gemm<64, 128, 2, 4, 4><<<dim3(Dc / 128, Nc / 64, 1), 256, SMF2>>>(
                gF1h, gF1l,
                gW2h + (size_t)l * DFFc * Dc, gW2l + (size_t)l * DFFc * Dc,
                gX, nullptr, nullptr, Nc, Dc, DFFc, b2l, gAttn, 6);
        } else {
            // write fp32 into attn_t (next layer's attn seed) + Xt planes
            bf16_gemm<64, 128, 2, 4, 4><<<dim3(Dc / 128, Nc / 64, 1), 256, SMF2>>>(
                gF1h, gF1l,
                gW2h + (size_t)l * DFFc * Dc, gW2l + (size_t)l * DFFc * Dc,
                gAttn, gXh, gXl, Nc, Dc, DFFc, b2l, gAttn, 14);
        }
    }

    // final transpose X_t[n][d] -> d_out[d][n]
    tfinal<<<dim3(Dc / 32, Nc / 32, 1), dim3(32, 8)>>>(gX, (float*)d_out);
}

// round 14
// speedup vs baseline: 1.1710x; 1.0186x over previous
#include <cuda_runtime.h>
#include <cuda_bf16.h>
#include <mma.h>
#include <cstdint>

using namespace nvcuda;

#define Lc   8
#define Hc   4
#define Qc   64
#define Dc   512
#define Nc   2048
#define DFFc 2048
#define KVROWS (Hc * Dc + Hc * Qc)   // 2304 output cols: Y then KX
#define YROWS  (Hc * Dc)             // 2048

// ---------------- device scratch (no allocations allowed) ----------------
// Activations N-major: acts[n][feature]; weights natural [out][K].
__device__ float g_X[Nc * Dc];
__device__ float g_attn[Nc * Dc];
__device__ float g_Y[Nc * YROWS];
__device__ __nv_bfloat16 g_KVh[Lc * KVROWS * Dc], g_KVl[Lc * KVROWS * Dc]; // [l][2304][512]
__device__ __nv_bfloat16 g_W1h[Lc * DFFc * Dc],   g_W1l[Lc * DFFc * Dc];   // [l][2048][512]
__device__ __nv_bfloat16 g_W2h[Lc * Dc * DFFc],   g_W2l[Lc * Dc * DFFc];   // [l][512][2048]
__device__ __nv_bfloat16 g_Xh[Nc * Dc],           g_Xl[Nc * Dc];
__device__ __nv_bfloat16 g_Ath[Nc * Dc],          g_Atl[Nc * Dc];
__device__ __nv_bfloat16 g_F1h[Nc * DFFc],        g_F1l[Nc * DFFc];
__device__ __nv_bfloat16 g_KXh[Nc * 256],         g_KXl[Nc * 256];

// ---------------- helpers --------------------------------------------------
__device__ __forceinline__ uint32_t smem_u32(const void* p) {
    uint32_t a;
    asm("{ .reg .u64 t; cvta.to.shared.u64 t, %1; cvt.u32.u64 %0, t; }"
        : "=r"(a) : "l"(p));
    return a;
}
__device__ __forceinline__ void cp16(void* s, const void* g) {
    asm volatile("cp.async.cg.shared.global [%0], [%1], 16;"
                 :: "r"(smem_u32(s)), "l"(g) : "memory");
}
__device__ __forceinline__ void cp_commit() {
    asm volatile("cp.async.commit_group;" ::: "memory");
}
template<int N> __device__ __forceinline__ void cp_wait() {
    asm volatile("cp.async.wait_group %0;" :: "n"(N) : "memory");
}

__device__ __forceinline__ void split_store4(__nv_bfloat16* __restrict__ Hd,
                                             __nv_bfloat16* __restrict__ Ld,
                                             float4 v)
{
    __nv_bfloat162 h0 = __floats2bfloat162_rn(v.x, v.y);
    __nv_bfloat162 h1 = __floats2bfloat162_rn(v.z, v.w);
    float2 f0 = __bfloat1622float2(h0);
    float2 f1 = __bfloat1622float2(h1);
    __nv_bfloat162 l0 = __floats2bfloat162_rn(v.x - f0.x, v.y - f0.y);
    __nv_bfloat162 l1 = __floats2bfloat162_rn(v.z - f1.x, v.w - f1.y);
    *(__nv_bfloat162*)(Hd)     = h0;
    *(__nv_bfloat162*)(Hd + 2) = h1;
    *(__nv_bfloat162*)(Ld)     = l0;
    *(__nv_bfloat162*)(Ld + 2) = l1;
}
__device__ __forceinline__ void split1s(float v, __nv_bfloat16* H, __nv_bfloat16* L) {
    __nv_bfloat16 hv = __float2bfloat16(v);
    *H = hv;
    *L = __float2bfloat16(v - __bfloat162float(hv));
}

__device__ __forceinline__ unsigned enc_f(float f) {
    unsigned u = __float_as_uint(f);
    return (u & 0x80000000u) ? ~u : (u | 0x80000000u);
}
__device__ __forceinline__ float dec_f(unsigned v) {
    return __uint_as_float((v & 0x80000000u) ? (v ^ 0x80000000u) : ~v);
}

// ---------------- plain split ----------------------------------------------
__global__ void __launch_bounds__(256) split_kernel(
    const float4* __restrict__ src,
    __nv_bfloat16* __restrict__ h, __nv_bfloat16* __restrict__ l, int n4)
{
    int i = blockIdx.x * 256 + threadIdx.x;
    if (i < n4) {
        float4 v = src[i];
        split_store4(h + (size_t)i * 4, l + (size_t)i * 4, v);
    }
}

// ---------------- KV row-concat split: [V_l rows; K_l rows] ----------------
__global__ void __launch_bounds__(256) pack_kv(
    const float4* __restrict__ V, const float4* __restrict__ K,
    __nv_bfloat16* __restrict__ h, __nv_bfloat16* __restrict__ l)
{
    constexpr int PER_L = KVROWS * (Dc / 4);
    int i = blockIdx.x * 256 + threadIdx.x;
    if (i >= Lc * PER_L) return;
    const int lay = i / PER_L;
    const int rem = i % PER_L;
    const int row = rem >> 7;
    const int c4  = rem & 127;
    float4 v = (row < YROWS)
        ? V[((size_t)lay * YROWS + row) * 128 + c4]
        : K[((size_t)lay * (Hc * Qc) + row - YROWS) * 128 + c4];
    split_store4(h + (size_t)i * 4, l + (size_t)i * 4, v);
}

// ---------------- X transpose + split (init only) ---------------------------
__global__ void __launch_bounds__(256) tsplit_generic(
    const float* __restrict__ src,
    __nv_bfloat16* __restrict__ dH, __nv_bfloat16* __restrict__ dL,
    float* __restrict__ copyT, int R, int C)
{
    __shared__ float t[32][33];
    const size_t bo = (size_t)blockIdx.z * R * C;
    const int tx = threadIdx.x, ty = threadIdx.y;
    const int x  = blockIdx.x * 32 + tx;
    const int y0 = blockIdx.y * 32;
#pragma unroll
    for (int j = 0; j < 4; j++)
        t[ty + j * 8][tx] = src[bo + (size_t)(y0 + ty + j * 8) * C + x];
    __syncthreads();
#pragma unroll
    for (int j = 0; j < 4; j++) {
        const int k = blockIdx.x * 32 + ty + j * 8;
        const int r = y0 + tx;
        const float v = t[tx][ty + j * 8];
        const size_t di = bo + (size_t)k * R + r;
        split1s(v, dH + di, dL + di);
        if (copyT) copyT[di] = v;
    }
}

// ---------------- final transpose: Xt[n][d] -> out[d][n] --------------------
__global__ void __launch_bounds__(256) tfinal(
    const float* __restrict__ Xt, float* __restrict__ out)
{
    __shared__ float t[32][33];
    const int tx = threadIdx.x, ty = threadIdx.y;
    const int x  = blockIdx.x * 32 + tx;
    const int y0 = blockIdx.y * 32;
#pragma unroll
    for (int j = 0; j < 4; j++)
        t[ty + j * 8][tx] = Xt[(size_t)(y0 + ty + j * 8) * Dc + x];
    __syncthreads();
#pragma unroll
    for (int j = 0; j < 4; j++) {
        const int d = blockIdx.x * 32 + ty + j * 8;
        const int n = y0 + tx;
        out[(size_t)d * Nc + n] = t[tx][ty + j * 8];
    }
}

// ============ bf16-plane 3x GEMM: C[m][n] = sum_k A[m][k]*B[n][k] ==========
// A:[M,K] act planes row-major; B:[N,K] weight planes row-major (fragment
// loaded col_major = implicit transpose). cp.async S-stage pipeline.
// mode bits: 1=relu(+col bias), 2=residual(+col bias), 4=write fp32 C,
//            8=write h+l planes.
// mode==64 -> KV: cols < YROWS direct fp32 store into C (pitch YROWS);
//             cols >= YROWS emit h/l planes (pitch 256) at col-YROWS.
template<int BM, int BN, int WM, int WN, int S, int MINB>
__global__ void __launch_bounds__(WM * WN * 32, MINB) bf16_gemm(
    const __nv_bfloat16* __restrict__ Ah, const __nv_bfloat16* __restrict__ Al,
    const __nv_bfloat16* __restrict__ Bh, const __nv_bfloat16* __restrict__ Bl,
    float* __restrict__ C,
    __nv_bfloat16* __restrict__ Ch, __nv_bfloat16* __restrict__ Cl,
    int M, int N, int K,
    const float* __restrict__ bias, const float* __restrict__ R, int mode)
{
    constexpr int TH = WM * WN * 32;
    constexpr int BK = 32;
    constexpr int AP = 40;                  // pitch over k (A rows)
    constexpr int BKP = 40;                 // pitch over k (B rows)
    constexpr int ABYT = BM * AP * 2;
    constexpr int BBYT = BN * BKP * 2;
    constexpr int STG = 2 * ABYT + 2 * BBYT;
    constexpr int MF = BM / (WM * 16);
    constexpr int NF = BN / (WN * 16);
    constexpr int AIT = BM * (BK / 8) / TH;
    constexpr int BIT = BN * (BK / 8) / TH;

    extern __shared__ char sm[];
    const int tid = threadIdx.x, w = tid >> 5;
    const int bm = blockIdx.y * BM;
    const int bn = blockIdx.x * BN;
    const int wm0 = (w % WM) * (MF * 16);
    const int wn0 = (w / WM) * (NF * 16);
    const int KT = K / BK;

    auto issue = [&](int tile) {
        const int k0 = tile * BK;
        char* st = sm + (tile % S) * STG;
        __nv_bfloat16* sAh = (__nv_bfloat16*)st;
        __nv_bfloat16* sAl = (__nv_bfloat16*)(st + ABYT);
        __nv_bfloat16* sBh = (__nv_bfloat16*)(st + 2 * ABYT);
        __nv_bfloat16* sBl = (__nv_bfloat16*)(st + 2 * ABYT + BBYT);
#pragma unroll
        for (int p = 0; p < AIT; p++) {
            const int c = tid + p * TH;
            const int r = c >> 2, c8 = (c & 3) * 8;
            cp16(sAh + r * AP + c8, Ah + (size_t)(bm + r) * K + k0 + c8);
            cp16(sAl + r * AP + c8, Al + (size_t)(bm + r) * K + k0 + c8);
        }
#pragma unroll
        for (int p = 0; p < BIT; p++) {
            const int c = tid + p * TH;
            const int r = c >> 2, c8 = (c & 3) * 8;
            cp16(sBh + r * BKP + c8, Bh + (size_t)(bn + r) * K + k0 + c8);
            cp16(sBl + r * BKP + c8, Bl + (size_t)(bn + r) * K + k0 + c8);
        }
    };

    wmma::fragment<wmma::accumulator, 16, 16, 16, float> acc[MF][NF];
#pragma unroll
    for (int i = 0; i < MF; i++)
#pragma unroll
        for (int j = 0; j < NF; j++) wmma::fill_fragment(acc[i][j], 0.f);

#pragma unroll
    for (int t = 0; t < S - 1; t++) {
        if (t < KT) issue(t);
        cp_commit();
    }

#pragma unroll 1
    for (int kt = 0; kt < KT; kt++) {
        cp_wait<S - 2>();
        __syncthreads();
        if (kt + S - 1 < KT) issue(kt + S - 1);
        cp_commit();

        char* st = sm + (kt % S) * STG;
        const __nv_bfloat16* sAh = (const __nv_bfloat16*)st;
        const __nv_bfloat16* sAl = (const __nv_bfloat16*)(st + ABYT);
        const __nv_bfloat16* sBh = (const __nv_bfloat16*)(st + 2 * ABYT);
        const __nv_bfloat16* sBl = (const __nv_bfloat16*)(st + 2 * ABYT + BBYT);

#pragma unroll
        for (int kks = 0; kks < 2; kks++) {
            const int kk = kks * 16;
            wmma::fragment<wmma::matrix_a, 16, 16, 16, __nv_bfloat16, wmma::row_major> fAh[MF];
            wmma::fragment<wmma::matrix_b, 16, 16, 16, __nv_bfloat16, wmma::col_major> fBh[NF];
#pragma unroll
            for (int i = 0; i < MF; i++)
                wmma::load_matrix_sync(fAh[i], sAh + (wm0 + i * 16) * AP + kk, AP);
#pragma unroll
            for (int j = 0; j < NF; j++)
                wmma::load_matrix_sync(fBh[j], sBh + (wn0 + j * 16) * BKP + kk, BKP);
#pragma unroll
            for (int i = 0; i < MF; i++)
#pragma unroll
                for (int j = 0; j < NF; j++)
                    wmma::mma_sync(acc[i][j], fAh[i], fBh[j], acc[i][j]);
            {
                wmma::fragment<wmma::matrix_b, 16, 16, 16, __nv_bfloat16, wmma::col_major> fBl[NF];
#pragma unroll
                for (int j = 0; j < NF; j++)
                    wmma::load_matrix_sync(fBl[j], sBl + (wn0 + j * 16) * BKP + kk, BKP);
#pragma unroll
                for (int i = 0; i < MF; i++)
#pragma unroll
                    for (int j = 0; j < NF; j++)
                        wmma::mma_sync(acc[i][j], fAh[i], fBl[j], acc[i][j]);
            }
            {
                wmma::fragment<wmma::matrix_a, 16, 16, 16, __nv_bfloat16, wmma::row_major> fAl[MF];
#pragma unroll
                for (int i = 0; i < MF; i++)
                    wmma::load_matrix_sync(fAl[i], sAl + (wm0 + i * 16) * AP + kk, AP);
#pragma unroll
                for (int i = 0; i < MF; i++)
#pragma unroll
                    for (int j = 0; j < NF; j++)
                        wmma::mma_sync(acc[i][j], fAl[i], fBh[j], acc[i][j]);
            }
        }
    }

    if (mode == 64) {
        if (bn < YROWS) {
#pragma unroll
            for (int i = 0; i < MF; i++)
#pragma unroll
                for (int j = 0; j < NF; j++)
                    wmma::store_matrix_sync(
                        &C[(size_t)(bm + wm0 + i * 16) * YROWS + bn + wn0 + j * 16],
                        acc[i][j], YROWS, wmma::mem_row_major);
        } else {
            __syncthreads();
            float* cs = (float*)sm;
#pragma unroll
            for (int i = 0; i < MF; i++)
#pragma unroll
                for (int j = 0; j < NF; j++)
                    wmma::store_matrix_sync(
                        cs + (size_t)(wm0 + i * 16) * BN + wn0 + j * 16,
                        acc[i][j], BN, wmma::mem_row_major);
            __syncthreads();
            constexpr int CIT2 = BM * BN / 4 / TH;
#pragma unroll
            for (int p = 0; p < CIT2; p++) {
                const int id = tid + p * TH;
                const int row = id / (BN / 4), c4 = id % (BN / 4);
                float4 v = ((const float4*)cs)[id];
                const int gr = bm + row;
                const int gcl = bn - YROWS + c4 * 4;
                split_store4(Ch + (size_t)gr * 256 + gcl,
                             Cl + (size_t)gr * 256 + gcl, v);
            }
        }
        return;
    }

    __syncthreads();
    float* cs = (float*)sm;
#pragma unroll
    for (int i = 0; i < MF; i++)
#pragma unroll
        for (int j = 0; j < NF; j++)
            wmma::store_matrix_sync(cs + (size_t)(wm0 + i * 16) * BN + wn0 + j * 16,
                                    acc[i][j], BN, wmma::mem_row_major);
    __syncthreads();

    constexpr int CIT = BM * BN / 4 / TH;
#pragma unroll
    for (int p = 0; p < CIT; p++) {
        const int id = tid + p * TH;
        const int row = id / (BN / 4), c4 = id % (BN / 4);
        float4 v = ((const float4*)cs)[id];
        const int gr = bm + row;
        const int gc = bn + c4 * 4;
        if (mode & 3) {
            float4 bv = *(const float4*)&bias[gc];
            v.x += bv.x; v.y += bv.y; v.z += bv.z; v.w += bv.w;
        }
        if (mode & 1) {
            v.x = fmaxf(v.x, 0.f); v.y = fmaxf(v.y, 0.f);
            v.z = fmaxf(v.z, 0.f); v.w = fmaxf(v.w, 0.f);
        }
        if (mode & 2) {
            float4 r4 = *(const float4*)&R[(size_t)gr * N + gc];
            v.x += r4.x; v.y += r4.y; v.z += r4.z; v.w += r4.w;
        }
        if (mode & 4) *(float4*)&C[(size_t)gr * N + gc] = v;
        if (mode & 8) split_store4(Ch + (size_t)gr * N + gc,
                                   Cl + (size_t)gr * N + gc, v);
    }
}

// ====== fused gram + argmax + scatter (N-major, coalesced) ================
#define CAND 96
__global__ void __launch_bounds__(256) gram_argmax_scatter(
    const __nv_bfloat16* __restrict__ KXh, const __nv_bfloat16* __restrict__ KXl,
    const float* __restrict__ Y, float* __restrict__ attn)
{
    constexpr int AP = 72, BP = 72, CP = 132;
    extern __shared__ char sm[];
    __nv_bfloat16* aH = (__nv_bfloat16*)sm;
    __nv_bfloat16* aL = (__nv_bfloat16*)(sm + 9216);
    float*    Cs   = (float*)(sm + 92160);
    unsigned* rm   = (unsigned*)(sm + 125952);
    int*      cnt  = (int*)(sm + 126208);
    float*    wrow = (float*)(sm + 126464);
    int*      cm   = (int*)(sm + 126720);
    float*    csv  = (float*)(sm + 151296);

    const int h  = blockIdx.y;
    const int r0 = blockIdx.x * 64;
    const int co = h * 64;
    const int tid = threadIdx.x, w = tid >> 5, lane = tid & 31;
    const int wm0 = (w & 1) * 32, wn0 = (w >> 1) * 32;

    if (tid < 64) { rm[tid] = enc_f(-1e30f); cnt[tid] = 0; }

    auto issueB = [&](int mt, int s) {
        const int m0 = mt * 128;
        __nv_bfloat16* bH = (__nv_bfloat16*)(sm + 18432 + s * 36864);
        __nv_bfloat16* bL = (__nv_bfloat16*)(sm + 18432 + s * 36864 + 18432);
#pragma unroll
        for (int p = 0; p < 4; p++) {
            const int c = tid + p * 256;
            const int r = c >> 3, c8 = (c & 7) * 8;
            cp16(bH + r * BP + c8, KXh + (size_t)(m0 + r) * 256 + co + c8);
            cp16(bL + r * BP + c8, KXl + (size_t)(m0 + r) * 256 + co + c8);
        }
    };

#pragma unroll
    for (int p = 0; p < 2; p++) {
        const int c = tid + p * 256;
        const int r = c >> 3, c8 = (c & 7) * 8;
        cp16(aH + r * AP + c8, KXh + (size_t)(r0 + r) * 256 + co + c8);
        cp16(aL + r * AP + c8, KXl + (size_t)(r0 + r) * 256 + co + c8);
    }
    issueB(0, 0);
    cp_commit();

    for (int mt = 0; mt < Nc / 128; mt++) {
        if (mt + 1 < Nc / 128) issueB(mt + 1, (mt + 1) & 1);
        cp_commit();
        cp_wait<1>();
        __syncthreads();

        const __nv_bfloat16* bH = (const __nv_bfloat16*)(sm + 18432 + (mt & 1) * 36864);
        const __nv_bfloat16* bL = bH + 18432 / 2;

        wmma::fragment<wmma::accumulator, 16, 16, 16, float> acc[2][2];
#pragma unroll
        for (int i = 0; i < 2; i++)
#pragma unroll
            for (int j = 0; j < 2; j++) wmma::fill_fragment(acc[i][j], 0.f);

#pragma unroll
        for (int kks = 0; kks < 4; kks++) {
            const int kk = kks * 16;
            wmma::fragment<wmma::matrix_a, 16, 16, 16, __nv_bfloat16, wmma::row_major> fAh[2];
            wmma::fragment<wmma::matrix_b, 16, 16, 16, __nv_bfloat16, wmma::col_major> fBh[2];
#pragma unroll
            for (int i = 0; i < 2; i++)
                wmma::load_matrix_sync(fAh[i], aH + (wm0 + i * 16) * AP + kk, AP);
#pragma unroll
            for (int j = 0; j < 2; j++)
                wmma::load_matrix_sync(fBh[j], bH + (wn0 + j * 16) * BP + kk, BP);
#pragma unroll
            for (int i = 0; i < 2; i++)
#pragma unroll
                for (int j = 0; j < 2; j++)
                    wmma::mma_sync(acc[i][j], fAh[i], fBh[j], acc[i][j]);
            {
                wmma::fragment<wmma::matrix_b, 16, 16, 16, __nv_bfloat16, wmma::col_major> fBl[2];
#pragma unroll
                for (int j = 0; j < 2; j++)
                    wmma::load_matrix_sync(fBl[j], bL + (wn0 + j * 16) * BP + kk, BP);
#pragma unroll
                for (int i = 0; i < 2; i++)
#pragma unroll
                    for (int j = 0; j < 2; j++)
                        wmma::mma_sync(acc[i][j], fAh[i], fBl[j], acc[i][j]);
            }
            {
                wmma::fragment<wmma::matrix_a, 16, 16, 16, __nv_bfloat16, wmma::row_major> fAl[2];
#pragma unroll
                for (int i = 0; i < 2; i++)
                    wmma::load_matrix_sync(fAl[i], aL + (wm0 + i * 16) * AP + kk, AP);
#pragma unroll
                for (int i = 0; i < 2; i++)
#pragma unroll
                    for (int j = 0; j < 2; j++)
                        wmma::mma_sync(acc[i][j], fAl[i], fBh[j], acc[i][j]);
            }
        }
#pragma unroll
        for (int i = 0; i < 2; i++)
#pragma unroll
            for (int j = 0; j < 2; j++)
                wmma::store_matrix_sync(Cs + (wm0 + i * 16) * CP + wn0 + j * 16,
                                        acc[i][j], CP, wmma::mem_row_major);
        __syncthreads();

        const int r = tid >> 2;
        const int c0 = (tid & 3) * 32;
        float tm = -1e30f;
#pragma unroll
        for (int c = 0; c < 32; c++) tm = fmaxf(tm, Cs[r * CP + c0 + c]);
        tm = fmaxf(tm, __shfl_xor_sync(0xffffffffu, tm, 1, 4));
        tm = fmaxf(tm, __shfl_xor_sync(0xffffffffu, tm, 2, 4));
        if ((tid & 3) == 0) atomicMax(&rm[r], enc_f(tm));
        __syncthreads();

        const float thr = dec_f(rm[r]) - 0.5f;
        const int m0 = mt * 128;
#pragma unroll
        for (int c = 0; c < 32; c++) {
            const float v = Cs[r * CP + c0 + c];
            if (v >= thr) {
                int pos = atomicAdd(&cnt[r], 1);
                if (pos < CAND) {
                    cm[r * CAND + pos]  = m0 + c0 + c;
                    csv[r * CAND + pos] = v;
                }
            }
        }
        __syncthreads();
    }

    if (tid < 64) {
        const float fmax = dec_f(rm[tid]);
        const float thrF = fmax - 0.5f;
        const int nc = cnt[tid] < CAND ? cnt[tid] : CAND;
        int hits = 0;
        for (int j = 0; j < nc; j++) {
            if (csv[tid * CAND + j] >= thrF) {
                cm[tid * CAND + hits] = cm[tid * CAND + j];
                hits++;
            }
        }
        cnt[tid] = hits;
        wrow[tid] = (fabsf(fmax) > 0.5f && hits > 0) ? 1.f / (float)hits : 0.f;
    }
    __syncthreads();

    for (int rr = 0; rr < 8; rr++) {
        const int r = w * 8 + rr;
        const float wv = wrow[r];
        const int hits = cnt[r];
        if (wv == 0.f || hits == 0) continue;
        const int n = r0 + r;
        const float* yrow = Y + (size_t)n * YROWS + h * Dc;
        float yv[16];
#pragma unroll
        for (int p = 0; p < 16; p++)
            yv[p] = wv * yrow[lane + p * 32];
        for (int j = 0; j < hits; j++) {
            float* arow = attn + (size_t)cm[r * CAND + j] * Dc;
#pragma unroll
            for (int p = 0; p < 16; p++)
                atomicAdd(&arow[lane + p * 32], yv[p]);
        }
    }
}

// --------------------------------------------------------------------------
extern "C" void kernel_launch(void* const* d_in, const int* in_sizes, int n_in,
                              void* d_out, int out_size)
{
    const float* X  = (const float*)d_in[0];
    const float* Kp = (const float*)d_in[1];
    const float* Vp = (const float*)d_in[2];
    const float* W1 = (const float*)d_in[3];
    const float* b1 = (const float*)d_in[4];
    const float* W2 = (const float*)d_in[5];
    const float* b2 = (const float*)d_in[6];

    float *gX, *gAttn, *gY;
    __nv_bfloat16 *gKVh, *gKVl, *gW1h, *gW1l, *gW2h, *gW2l;
    __nv_bfloat16 *gXh, *gXl, *gAth, *gAtl, *gF1h, *gF1l, *gKXh, *gKXl;
    cudaGetSymbolAddress((void**)&gX,   g_X);
    cudaGetSymbolAddress((void**)&gAttn,g_attn);
    cudaGetSymbolAddress((void**)&gY,   g_Y);
    cudaGetSymbolAddress((void**)&gKVh, g_KVh);  cudaGetSymbolAddress((void**)&gKVl, g_KVl);
    cudaGetSymbolAddress((void**)&gW1h, g_W1h);  cudaGetSymbolAddress((void**)&gW1l, g_W1l);
    cudaGetSymbolAddress((void**)&gW2h, g_W2h);  cudaGetSymbolAddress((void**)&gW2l, g_W2l);
    cudaGetSymbolAddress((void**)&gXh,  g_Xh);   cudaGetSymbolAddress((void**)&gXl,  g_Xl);
    cudaGetSymbolAddress((void**)&gAth, g_Ath);  cudaGetSymbolAddress((void**)&gAtl, g_Atl);
    cudaGetSymbolAddress((void**)&gF1h, g_F1h);  cudaGetSymbolAddress((void**)&gF1l, g_F1l);
    cudaGetSymbolAddress((void**)&gKXh, g_KXh);  cudaGetSymbolAddress((void**)&gKXl, g_KXl);

    // smem: stage = 2*(BM*40*2) + 2*(BN*40*2)
    const int SMBIG = 2 * (2 * 128 * 40 * 2 + 2 * 128 * 40 * 2);  // 81920 (S=2)
    const int SMF2  = 4 * (2 *  64 * 40 * 2 + 2 * 128 * 40 * 2);  // 122880 (S=4)
    const int SMGR  = 175872;
    cudaFuncSetAttribute(bf16_gemm<128, 128, 2, 4, 2, 2>,
                         cudaFuncAttributeMaxDynamicSharedMemorySize, SMBIG);
    cudaFuncSetAttribute(bf16_gemm<64, 128, 2, 4, 4, 1>,
                         cudaFuncAttributeMaxDynamicSharedMemorySize, SMF2);
    cudaFuncSetAttribute(gram_argmax_scatter,
                         cudaFuncAttributeMaxDynamicSharedMemorySize, SMGR);

    {
        const int nKV = Lc * KVROWS * Dc / 4;
        const int nW  = Lc * DFFc * Dc / 4;
        pack_kv<<<(nKV + 255) / 256, 256>>>((const float4*)Vp, (const float4*)Kp,
                                            gKVh, gKVl);
        split_kernel<<<(nW + 255) / 256, 256>>>((const float4*)W1, gW1h, gW1l, nW);
        split_kernel<<<(nW + 255) / 256, 256>>>((const float4*)W2, gW2h, gW2l, nW);
        // X: [512][2048] -> Xt planes [2048][512] + attn_t fp32 seed
        tsplit_generic<<<dim3(2048 / 32, 512 / 32, 1), dim3(32, 8)>>>(
            X, gXh, gXl, gAttn, Dc, Nc);
    }

    for (int l = 0; l < Lc; l++) {
        const float* b1l = b1 + (size_t)l * DFFc;
        const float* b2l = b2 + (size_t)l * Dc;
        const bool last = (l == Lc - 1);

        // 1) [Y | KXt] = Xt @ KV^T  (mode 64, grid 18x16 = 288 blocks, 2/SM)
        bf16_gemm<128, 128, 2, 4, 2, 2><<<dim3(KVROWS / 128, Nc / 128, 1), 256, SMBIG>>>(
            gXh, gXl,
            gKVh + (size_t)l * KVROWS * Dc, gKVl + (size_t)l * KVROWS * Dc,
            gY, gKXh, gKXl, Nc, KVROWS, Dc, nullptr, nullptr, 64);

        // 2) fused gram+argmax+scatter
        gram_argmax_scatter<<<dim3(Nc / 64, Hc), 256, SMGR>>>(gKXh, gKXl, gY, gAttn);

        // 3) attn_t planes
        split_kernel<<<(Nc * Dc / 4 + 255) / 256, 256>>>(
            (const float4*)gAttn, gAth, gAtl, Nc * Dc / 4);

        // 4) ff1_t planes = relu(attn_t @ W1^T + b1[col])  (mode 9, 256 blocks 2/SM)
        bf16_gemm<128, 128, 2, 4, 2, 2><<<dim3(DFFc / 128, Nc / 128, 1), 256, SMBIG>>>(
            gAth, gAtl,
            gW1h + (size_t)l * DFFc * Dc, gW1l + (size_t)l * DFFc * Dc,
            nullptr, gF1h, gF1l, Nc, DFFc, Dc, b1l, nullptr, 9);

        // 5) X_t = attn_t + ff1_t @ W2^T + b2[col]
        if (last) {
            bf16_gemm<64, 128, 2, 4, 4, 1><<<dim3(Dc / 128, Nc / 64, 1), 256, SMF2>>>(
                gF1h, gF1l,
                gW2h + (size_t)l * Dc * DFFc, gW2l + (size_t)l * Dc * DFFc,
                gX, nullptr, nullptr, Nc, Dc, DFFc, b2l, gAttn, 6);
        } else {
            bf16_gemm<64, 128, 2, 4, 4, 1><<<dim3(Dc / 128, Nc / 64, 1), 256, SMF2>>>(
                gF1h, gF1l,
                gW2h + (size_t)l * Dc * DFFc, gW2l + (size_t)l * Dc * DFFc,
                gAttn, gXh, gXl, Nc, Dc, DFFc, b2l, gAttn, 14);
        }
    }

    // final transpose X_t[n][d] -> d_out[d][n]
    tfinal<<<dim3(Dc / 32, Nc / 32, 1), dim3(32, 8)>>>(gX, (float*)d_out);
}